// round 2
// baseline (speedup 1.0000x reference)
#include <cuda_runtime.h>
#include <cuda_bf16.h>
#include <math.h>

#define NN 100000
#define EE 500000
#define D  128
#define HH 8
#define DKH 16
#define BM 64
#define BK 16

// ---------------- scratch (device globals; no allocations allowed) ----------
__device__ float g_Weff[6][D*D];     // 0..2 = K-proj per relation, 3..5 = V-proj
__device__ float g_beff[6][D];
__device__ float g_KV[6][NN*D];      // 0..2 = K per relation, 3..5 = V per relation
__device__ float g_Q[2][NN*D];       // 0 = q for node type a, 1 = for type b
__device__ float g_ex[3][EE*HH];     // per-edge exp(score)
__device__ float g_den[3][NN*HH];    // softmax denominators
__device__ float g_t[2][NN*D];       // aggregated messages (0: type a, 1: type b)

// scratch selector usable from inside kernels (host cannot take symbol addrs
// during graph capture without extra APIs, so kernels resolve by index)
__device__ __forceinline__ float* scratch(int s) {
    switch (s) {
        case 0: return g_KV[0]; case 1: return g_KV[1]; case 2: return g_KV[2];
        case 3: return g_KV[3]; case 4: return g_KV[4]; case 5: return g_KV[5];
        case 6: return g_Q[0];  case 7: return g_Q[1];
        case 8: return g_t[0];  case 9: return g_t[1];
        case 10: return g_Weff[0]; case 11: return g_Weff[1]; case 12: return g_Weff[2];
        case 13: return g_Weff[3]; case 14: return g_Weff[4]; case 15: return g_Weff[5];
        case 16: return g_beff[0]; case 17: return g_beff[1]; case 18: return g_beff[2];
        case 19: return g_beff[3]; case 20: return g_beff[4]; case 21: return g_beff[5];
    }
    return nullptr;
}

// ---------------- init: zero den + t every launch ---------------------------
__global__ void zero_kernel() {
    const long DEN_TOT = 3L * NN * HH;            // 2.4M
    const long TOT = DEN_TOT + 2L * NN * D;       // + 25.6M
    float* denp = &g_den[0][0];
    float* tp   = &g_t[0][0];
    for (long i = blockIdx.x * (long)blockDim.x + threadIdx.x; i < TOT;
         i += (long)gridDim.x * blockDim.x) {
        if (i < DEN_TOT) denp[i] = 0.f;
        else             tp[i - DEN_TOT] = 0.f;
    }
}

// ---------------- fold per-head relation transforms into weights ------------
// Weff[buf][i][h*16+e] = sum_d W[tsrc][i][h*16+d] * rel[r][h][d][e]
__global__ void weff_kernel(const float* __restrict__ Wk, const float* __restrict__ bk,
                            const float* __restrict__ Wv, const float* __restrict__ bv,
                            const float* __restrict__ rel_att, const float* __restrict__ rel_msg) {
    int idx = blockIdx.x * blockDim.x + threadIdx.x;
    if (idx >= 6 * D * D) return;
    int buf = idx / (D * D);
    int rem = idx % (D * D);
    int i = rem / D;
    int o = rem % D;
    int h = o / DKH, e2 = o % DKH;
    int r = buf % 3;
    bool isV = buf >= 3;
    int tsrc = (r == 1) ? 1 : 0;       // rel1 sources from type b
    const float* Wm  = isV ? Wv : Wk;
    const float* bm  = isV ? bv : bk;
    const float* rel = isV ? rel_msg : rel_att;
    const float* wrow = Wm + tsrc * D * D + i * D + h * DKH;
    const float* relm = rel + (r * HH + h) * DKH * DKH;  // [d][e]
    float s = 0.f;
    #pragma unroll
    for (int d = 0; d < DKH; d++) s += wrow[d] * relm[d * DKH + e2];
    g_Weff[buf][i * D + o] = s;
    if (i == 0) {
        const float* brow = bm + tsrc * D + h * DKH;
        float sb = 0.f;
        #pragma unroll
        for (int d = 0; d < DKH; d++) sb += brow[d] * relm[d * DKH + e2];
        g_beff[buf][o] = sb;
    }
}

// ---------------- fp32 GEMM: C[M,128] = scale*(A[M,128]@W[128,128]) + bias --
// optional epilogue: C = C*alpha + resid*(1-alpha), alpha = sigmoid(skip[idx])
__global__ __launch_bounds__(256) void gemm_kernel(
    const float* Aopt, int Asel, const float* Wopt, int Wsel,
    const float* bOpt, int bsel, float* Copt, int Csel,
    int M, float scaleAcc,
    const float* __restrict__ resid, const float* __restrict__ skipv, int skipIdx)
{
    const float* A    = (Asel >= 0) ? scratch(Asel) : Aopt;
    const float* W    = (Wsel >= 0) ? scratch(Wsel) : Wopt;
    const float* bias = (bsel >= 0) ? scratch(bsel) : bOpt;
    float*       C    = (Csel >= 0) ? scratch(Csel) : Copt;

    __shared__ __align__(16) float As[BK][BM + 4];   // row stride 68 floats = 17*16B
    __shared__ __align__(16) float Bs[BK][D];

    int tid = threadIdx.x;
    int m0  = blockIdx.x * BM;
    int tx  = tid & 15;     // col block: tx*8
    int ty  = tid >> 4;     // row block: ty*4

    float acc[4][8];
    #pragma unroll
    for (int i = 0; i < 4; i++)
        #pragma unroll
        for (int j = 0; j < 8; j++) acc[i][j] = 0.f;

    for (int k0 = 0; k0 < D; k0 += BK) {
        {   // A tile: 64 rows x 16 cols = 256 float4, one per thread
            int mi = tid >> 2;
            int kq = tid & 3;
            int row = m0 + mi;
            float4 v = (row < M) ? *(const float4*)(A + (size_t)row * D + k0 + kq * 4)
                                 : make_float4(0.f, 0.f, 0.f, 0.f);
            As[kq * 4 + 0][mi] = v.x; As[kq * 4 + 1][mi] = v.y;
            As[kq * 4 + 2][mi] = v.z; As[kq * 4 + 3][mi] = v.w;
        }
        {   // W tile: 16 rows x 128 cols = 512 float4, two per thread
            #pragma unroll
            for (int u = 0; u < 2; u++) {
                int f  = tid + u * 256;
                int kr = f >> 5;
                int c4 = f & 31;
                *(float4*)&Bs[kr][c4 * 4] = *(const float4*)(W + (size_t)(k0 + kr) * D + c4 * 4);
            }
        }
        __syncthreads();
        #pragma unroll
        for (int kk = 0; kk < BK; kk++) {
            float a[4], b[8];
            #pragma unroll
            for (int i = 0; i < 4; i++) a[i] = As[kk][ty * 4 + i];
            #pragma unroll
            for (int j = 0; j < 8; j++) b[j] = Bs[kk][tx * 8 + j];
            #pragma unroll
            for (int i = 0; i < 4; i++)
                #pragma unroll
                for (int j = 0; j < 8; j++) acc[i][j] += a[i] * b[j];
        }
        __syncthreads();
    }

    float alpha = 1.f, oneMinus = 0.f;
    if (resid) {
        float s = skipv[skipIdx];
        alpha = 1.f / (1.f + expf(-s));
        oneMinus = 1.f - alpha;
    }
    #pragma unroll
    for (int i = 0; i < 4; i++) {
        int row = m0 + ty * 4 + i;
        if (row >= M) continue;
        #pragma unroll
        for (int j = 0; j < 8; j++) {
            int col = tx * 8 + j;
            float v = acc[i][j] * scaleAcc + bias[col];
            if (resid) v = v * alpha + resid[(size_t)row * D + col] * oneMinus;
            C[(size_t)row * D + col] = v;
        }
    }
}

// ---------------- edge pass A: score -> exp, accumulate denominators --------
// one thread per (edge, head); softmax is shift-invariant and scores are O(6),
// so no segment-max pass is needed (exp stays well within fp32 range)
__global__ void edge_score_kernel(int r, const int* __restrict__ src, const int* __restrict__ dst,
                                  int qsel, const float* __restrict__ rel_pri) {
    int idx = blockIdx.x * blockDim.x + threadIdx.x;
    if (idx >= EE * HH) return;
    int e = idx >> 3, h = idx & 7;
    int s = src[e], d = dst[e];
    const float4* kp = (const float4*)(g_KV[r]   + (size_t)s * D + h * DKH);
    const float4* qp = (const float4*)(g_Q[qsel] + (size_t)d * D + h * DKH);
    float acc = 0.f;
    #pragma unroll
    for (int j = 0; j < 4; j++) {
        float4 a = kp[j], b = qp[j];
        acc += a.x * b.x + a.y * b.y + a.z * b.z + a.w * b.w;
    }
    float sc = acc * rel_pri[r * HH + h] * 0.25f;   // / sqrt(16)
    float ex = expf(sc);
    g_ex[r][idx] = ex;
    atomicAdd(&g_den[r][(size_t)d * HH + h], ex);
}

// ---------------- edge pass B: normalize + scatter v[src]*a into t[dst] -----
// one thread per (edge, 4-channel group); vector red.global keeps atomic count low
__global__ void edge_aggr_kernel(int r, const int* __restrict__ src, const int* __restrict__ dst,
                                 int tsel) {
    long idx = blockIdx.x * (long)blockDim.x + threadIdx.x;
    if (idx >= (long)EE * 32) return;
    int e  = (int)(idx >> 5);
    int c4 = (int)(idx & 31);
    int h  = c4 >> 2;
    int s = src[e], d = dst[e];
    float a = g_ex[r][e * HH + h] / g_den[r][(size_t)d * HH + h];
    float4 v = *(const float4*)(g_KV[3 + r] + (size_t)s * D + c4 * 4);
    float* tp = g_t[tsel] + (size_t)d * D + c4 * 4;
    asm volatile("red.global.add.v4.f32 [%0], {%1,%2,%3,%4};"
                 :: "l"(tp), "f"(v.x * a), "f"(v.y * a), "f"(v.z * a), "f"(v.w * a)
                 : "memory");
}

// ---------------- launch --------------------------------------------------
extern "C" void kernel_launch(void* const* d_in, const int* in_sizes, int n_in,
                              void* d_out, int out_size) {
    const float* h_a = (const float*)d_in[0];
    const float* h_b = (const float*)d_in[1];
    const int* src0 = (const int*)d_in[2]; const int* dst0 = (const int*)d_in[3];
    const int* src1 = (const int*)d_in[4]; const int* dst1 = (const int*)d_in[5];
    const int* src2 = (const int*)d_in[6]; const int* dst2 = (const int*)d_in[7];
    const float* Wk = (const float*)d_in[8];  const float* bk = (const float*)d_in[9];
    const float* Wv = (const float*)d_in[10]; const float* bv = (const float*)d_in[11];
    const float* Wq = (const float*)d_in[12]; const float* bq = (const float*)d_in[13];
    const float* Wa = (const float*)d_in[14]; const float* ba = (const float*)d_in[15];
    const float* rel_att = (const float*)d_in[16];
    const float* rel_msg = (const float*)d_in[17];
    const float* rel_pri = (const float*)d_in[18];
    const float* skip    = (const float*)d_in[19];
    float* out = (float*)d_out;

    zero_kernel<<<2048, 256>>>();
    weff_kernel<<<(6 * D * D + 255) / 256, 256>>>(Wk, bk, Wv, bv, rel_att, rel_msg);

    int gb = (NN + BM - 1) / BM;
    // K projections (relation-fused weights): scratch W 10..12, bias 16..18, C 0..2
    gemm_kernel<<<gb, 256>>>(h_a, -1, nullptr, 10, nullptr, 16, nullptr, 0, NN, 1.f, nullptr, nullptr, 0);
    gemm_kernel<<<gb, 256>>>(h_b, -1, nullptr, 11, nullptr, 17, nullptr, 1, NN, 1.f, nullptr, nullptr, 0);
    gemm_kernel<<<gb, 256>>>(h_a, -1, nullptr, 12, nullptr, 18, nullptr, 2, NN, 1.f, nullptr, nullptr, 0);
    // V projections: W 13..15, bias 19..21, C 3..5
    gemm_kernel<<<gb, 256>>>(h_a, -1, nullptr, 13, nullptr, 19, nullptr, 3, NN, 1.f, nullptr, nullptr, 0);
    gemm_kernel<<<gb, 256>>>(h_b, -1, nullptr, 14, nullptr, 20, nullptr, 4, NN, 1.f, nullptr, nullptr, 0);
    gemm_kernel<<<gb, 256>>>(h_a, -1, nullptr, 15, nullptr, 21, nullptr, 5, NN, 1.f, nullptr, nullptr, 0);
    // Q projections: q_a uses Wq[0] (dst of rel1), q_b uses Wq[1] (dst of rel0/2)
    gemm_kernel<<<gb, 256>>>(h_a, -1, Wq,          -1, bq,     -1, nullptr, 6, NN, 1.f, nullptr, nullptr, 0);
    gemm_kernel<<<gb, 256>>>(h_b, -1, Wq + D * D,  -1, bq + D, -1, nullptr, 7, NN, 1.f, nullptr, nullptr, 0);

    // edge softmax numerators + denominators
    int esb = (EE * HH + 255) / 256;
    edge_score_kernel<<<esb, 256>>>(0, src0, dst0, 1, rel_pri);
    edge_score_kernel<<<esb, 256>>>(1, src1, dst1, 0, rel_pri);
    edge_score_kernel<<<esb, 256>>>(2, src2, dst2, 1, rel_pri);

    // weighted message aggregation (rel1 -> t_a; rel0+rel2 -> t_b)
    int eab = (int)(((long)EE * 32 + 255) / 256);
    edge_aggr_kernel<<<eab, 256>>>(0, src0, dst0, 1);
    edge_aggr_kernel<<<eab, 256>>>(1, src1, dst1, 0);
    edge_aggr_kernel<<<eab, 256>>>(2, src2, dst2, 1);

    // output projections with skip mixing; 0.5 = cross-reducer mean for type b
    gemm_kernel<<<gb, 256>>>(nullptr, 8, Wa,         -1, ba,     -1, out,                 -1, NN, 1.0f, h_a, skip, 0);
    gemm_kernel<<<gb, 256>>>(nullptr, 9, Wa + D * D, -1, ba + D, -1, out + (size_t)NN * D, -1, NN, 0.5f, h_b, skip, 1);
}

// round 5
// speedup vs baseline: 1.5798x; 1.5798x over previous
#include <cuda_runtime.h>
#include <cuda_bf16.h>
#include <math.h>
#include <stdint.h>

#define NN 100000
#define EE 500000
#define D  128
#define HH 8
#define DKH 16

// ---------------- scratch (device globals; no allocations allowed) ----------
__device__ float g_Pa[(size_t)NN * 640];   // [K_r0 | K_r2 | V_r0 | V_r2 | Q_a] per node (type a)
__device__ float g_Pb[(size_t)NN * 384];   // [K_r1 | V_r1 | Q_b] per node (type b)
__device__ float g_Wcat_a[D * 640];
__device__ float g_Wcat_b[D * 384];
__device__ float g_bcat_a[640];
__device__ float g_bcat_b[384];
__device__ float g_t[3][(size_t)NN * D];   // per-relation unnormalized message sums
__device__ float g_den[3][(size_t)NN * HH];// per-relation softmax denominators

__device__ __forceinline__ float* scratch(int s) {
    switch (s) {
        case 0: return g_Pa;      case 1: return g_Pb;
        case 2: return g_Wcat_a;  case 3: return g_Wcat_b;
        case 4: return g_bcat_a;  case 5: return g_bcat_b;
    }
    return nullptr;
}

// ---------------- init: zero den + t every launch ---------------------------
__global__ void zero_kernel() {
    const long T_TOT   = 3L * NN * D;     // 38.4M
    const long DEN_TOT = 3L * NN * HH;    // 2.4M
    float4* tp = (float4*)&g_t[0][0];
    float4* dp = (float4*)&g_den[0][0];
    long stride = (long)gridDim.x * blockDim.x;
    long i0 = blockIdx.x * (long)blockDim.x + threadIdx.x;
    const float4 z = make_float4(0.f, 0.f, 0.f, 0.f);
    for (long i = i0; i < T_TOT / 4; i += stride) tp[i] = z;
    for (long i = i0; i < DEN_TOT / 4; i += stride) dp[i] = z;
}

// ---------------- fold relation transforms into concatenated weights --------
__global__ void wcat_kernel(const float* __restrict__ Wk, const float* __restrict__ bk,
                            const float* __restrict__ Wv, const float* __restrict__ bv,
                            const float* __restrict__ Wq, const float* __restrict__ bq,
                            const float* __restrict__ rel_att, const float* __restrict__ rel_msg) {
    int idx = blockIdx.x * blockDim.x + threadIdx.x;
    const int NA = D * 640;
    const int NB = D * 384;
    if (idx >= NA + NB) return;
    bool isA = idx < NA;
    int i, o, Ntot;
    if (isA) { i = idx / 640; o = idx % 640; Ntot = 640; }
    else     { int j = idx - NA; i = j / 384; o = j % 384; Ntot = 384; }
    int seg = o >> 7;          // a: 0=K_r0 1=K_r2 2=V_r0 3=V_r2 4=Q ; b: 0=K_r1 1=V_r1 2=Q
    int oo  = o & 127;
    int tsrc = isA ? 0 : 1;
    float val, bval;
    bool isQ = isA ? (seg == 4) : (seg == 2);
    if (isQ) {
        val  = Wq[tsrc * D * D + i * D + oo];
        bval = bq[tsrc * D + oo];
    } else {
        int r; bool isV;
        if (isA) { r = (seg == 0) ? 0 : (seg == 1) ? 2 : (seg == 2) ? 0 : 2; isV = (seg >= 2); }
        else     { r = 1; isV = (seg == 1); }
        const float* Wm  = isV ? Wv : Wk;
        const float* bm  = isV ? bv : bk;
        const float* rel = isV ? rel_msg : rel_att;
        int h = oo >> 4, e = oo & 15;
        const float* wrow = Wm + tsrc * D * D + i * D + h * DKH;
        const float* brow = bm + tsrc * D + h * DKH;
        const float* relm = rel + (r * HH + h) * DKH * DKH;
        float s = 0.f, sb = 0.f;
        #pragma unroll
        for (int d = 0; d < DKH; d++) {
            float rv = relm[d * DKH + e];
            s  += wrow[d] * rv;
            sb += brow[d] * rv;
        }
        val = s; bval = sb;
    }
    float* Wout = isA ? g_Wcat_a : g_Wcat_b;
    float* bout = isA ? g_bcat_a : g_bcat_b;
    Wout[i * Ntot + o] = val;
    if (i == 0) bout[o] = bval;
}

// ---------------- 3xTF32 tensor-core GEMM ----------------------------------
// C[M, Ntot] = Aeff[M,128] @ W[128,Ntot] + bias ; optional skip-mix epilogue.
// amode: 0 = A from pointer; 1 = t[1]/den[1]; 2 = 0.5*(t[0]/den[0] + t[2]/den[2])
// den==0 (no in-edges) maps to t=0 exactly, matching reference segment_sum.
__device__ __forceinline__ void split_tf32(float x, uint32_t& hi, uint32_t& lo) {
    uint32_t h;
    asm("cvt.rna.tf32.f32 %0, %1;" : "=r"(h) : "f"(x));
    float lf = x - __uint_as_float(h);
    uint32_t l;
    asm("cvt.rna.tf32.f32 %0, %1;" : "=r"(l) : "f"(lf));
    hi = h; lo = l;
}

__device__ __forceinline__ void mma_tf32(float* c, const uint32_t* a, const uint32_t* b) {
    asm volatile("mma.sync.aligned.m16n8k8.row.col.f32.tf32.tf32.f32 "
                 "{%0,%1,%2,%3},{%4,%5,%6,%7},{%8,%9},{%0,%1,%2,%3};"
                 : "+f"(c[0]), "+f"(c[1]), "+f"(c[2]), "+f"(c[3])
                 : "r"(a[0]), "r"(a[1]), "r"(a[2]), "r"(a[3]), "r"(b[0]), "r"(b[1]));
}

__global__ __launch_bounds__(256) void gemm_tc(
    const float* Aopt, int amode,
    int Wsel, const float* Wopt,
    int bsel, const float* bOpt,
    int Csel, float* Copt,
    int M, int Ntot,
    const float* __restrict__ resid, const float* __restrict__ skipv, int skipIdx)
{
    const float* W    = (Wsel >= 0) ? scratch(Wsel) : Wopt;
    const float* bias = (bsel >= 0) ? scratch(bsel) : bOpt;
    float*       C    = (Csel >= 0) ? scratch(Csel) : Copt;

    __shared__ __align__(16) float As[128][20];   // stride 20: conflict-free frag loads
    __shared__ __align__(16) float Bs[16][68];

    int tid = threadIdx.x, lane = tid & 31, wid = tid >> 5;
    int warp_m = wid >> 1, warp_n = wid & 1;
    int g = lane >> 2, tg = lane & 3;
    int m0 = blockIdx.x * 128, n0 = blockIdx.y * 64;

    float acc[2][4][4];
    #pragma unroll
    for (int mt = 0; mt < 2; mt++)
        #pragma unroll
        for (int nt = 0; nt < 4; nt++)
            #pragma unroll
            for (int i = 0; i < 4; i++) acc[mt][nt][i] = 0.f;

    for (int k0 = 0; k0 < 128; k0 += 16) {
        // A tile: 128 rows x 16 cols = 512 float4, two per thread
        #pragma unroll
        for (int u = 0; u < 2; u++) {
            int f = tid + u * 256;
            int m = f >> 2, q = f & 3;
            int row = m0 + m;
            int kk = k0 + q * 4;
            float4 v = make_float4(0.f, 0.f, 0.f, 0.f);
            if (row < M) {
                if (amode == 0) {
                    v = *(const float4*)(Aopt + (size_t)row * D + kk);
                } else if (amode == 1) {
                    float4 t = *(const float4*)(g_t[1] + (size_t)row * D + kk);
                    float den = g_den[1][(size_t)row * HH + (kk >> 4)];
                    float dn = (den > 0.f) ? (1.f / den) : 0.f;   // empty dst group -> t = 0
                    v = make_float4(t.x * dn, t.y * dn, t.z * dn, t.w * dn);
                } else {
                    float4 t0 = *(const float4*)(g_t[0] + (size_t)row * D + kk);
                    float4 t2 = *(const float4*)(g_t[2] + (size_t)row * D + kk);
                    float den0 = g_den[0][(size_t)row * HH + (kk >> 4)];
                    float den2 = g_den[2][(size_t)row * HH + (kk >> 4)];
                    float d0 = (den0 > 0.f) ? (0.5f / den0) : 0.f;
                    float d2 = (den2 > 0.f) ? (0.5f / den2) : 0.f;
                    v = make_float4(t0.x * d0 + t2.x * d2, t0.y * d0 + t2.y * d2,
                                    t0.z * d0 + t2.z * d2, t0.w * d0 + t2.w * d2);
                }
            }
            *(float4*)&As[m][q * 4] = v;
        }
        // B tile: 16 rows x 64 cols = 256 float4, one per thread
        {
            int kr = tid >> 4, c4 = tid & 15;
            float4 wv = *(const float4*)(W + (size_t)(k0 + kr) * Ntot + n0 + c4 * 4);
            *(float4*)&Bs[kr][c4 * 4] = wv;
        }
        __syncthreads();
        #pragma unroll
        for (int ks = 0; ks < 2; ks++) {
            int kb = ks * 8;
            uint32_t ahi[2][4], alo[2][4], bhi[4][2], blo[4][2];
            #pragma unroll
            for (int mt = 0; mt < 2; mt++) {
                int rb = warp_m * 32 + mt * 16;
                split_tf32(As[rb + g][kb + tg],         ahi[mt][0], alo[mt][0]);
                split_tf32(As[rb + g + 8][kb + tg],     ahi[mt][1], alo[mt][1]);
                split_tf32(As[rb + g][kb + tg + 4],     ahi[mt][2], alo[mt][2]);
                split_tf32(As[rb + g + 8][kb + tg + 4], ahi[mt][3], alo[mt][3]);
            }
            #pragma unroll
            for (int nt = 0; nt < 4; nt++) {
                int cb = warp_n * 32 + nt * 8;
                split_tf32(Bs[kb + tg][cb + g],     bhi[nt][0], blo[nt][0]);
                split_tf32(Bs[kb + tg + 4][cb + g], bhi[nt][1], blo[nt][1]);
            }
            #pragma unroll
            for (int mt = 0; mt < 2; mt++)
                #pragma unroll
                for (int nt = 0; nt < 4; nt++) {
                    mma_tf32(acc[mt][nt], ahi[mt], bhi[nt]);
                    mma_tf32(acc[mt][nt], alo[mt], bhi[nt]);
                    mma_tf32(acc[mt][nt], ahi[mt], blo[nt]);
                }
        }
        __syncthreads();
    }

    float alpha = 1.f, om = 0.f;
    if (resid) {
        float s = skipv[skipIdx];
        alpha = 1.f / (1.f + expf(-s));
        om = 1.f - alpha;
    }
    #pragma unroll
    for (int mt = 0; mt < 2; mt++)
        #pragma unroll
        for (int nt = 0; nt < 4; nt++) {
            int col = n0 + warp_n * 32 + nt * 8 + tg * 2;
            float b0 = bias[col], b1 = bias[col + 1];
            #pragma unroll
            for (int half = 0; half < 2; half++) {
                int row = m0 + warp_m * 32 + mt * 16 + g + half * 8;
                if (row >= M) continue;
                float v0 = acc[mt][nt][half * 2 + 0] + b0;
                float v1 = acc[mt][nt][half * 2 + 1] + b1;
                if (resid) {
                    v0 = v0 * alpha + resid[(size_t)row * D + col] * om;
                    v1 = v1 * alpha + resid[(size_t)row * D + col + 1] * om;
                }
                *(float2*)(C + (size_t)row * Ntot + col) = make_float2(v0, v1);
            }
        }
}

// ---------------- fused edge pass: score -> exp -> scatter ------------------
// one warp per edge; lanes cover 128 channels (head = lane>>2)
__global__ void edge_kernel(int r, const int* __restrict__ src, const int* __restrict__ dst,
                            const float* __restrict__ rel_pri) {
    int e = blockIdx.x * 8 + (threadIdx.x >> 5);
    if (e >= EE) return;
    int lane = threadIdx.x & 31;
    int h = lane >> 2;

    const float *kbase, *vbase, *qbase;
    int sstride, dstride;
    if (r == 0)      { kbase = g_Pa;       vbase = g_Pa + 256; qbase = g_Pb + 256; sstride = 640; dstride = 384; }
    else if (r == 1) { kbase = g_Pb;       vbase = g_Pb + 128; qbase = g_Pa + 512; sstride = 384; dstride = 640; }
    else             { kbase = g_Pa + 128; vbase = g_Pa + 384; qbase = g_Pb + 256; sstride = 640; dstride = 384; }
    float* tbuf = g_t[r];
    float* dbuf = g_den[r];

    int s = src[e], d = dst[e];
    float4 kv = *(const float4*)(kbase + (size_t)s * sstride + lane * 4);
    float4 qv = *(const float4*)(qbase + (size_t)d * dstride + lane * 4);
    float dot = kv.x * qv.x + kv.y * qv.y + kv.z * qv.z + kv.w * qv.w;
    dot += __shfl_xor_sync(0xffffffff, dot, 1);
    dot += __shfl_xor_sync(0xffffffff, dot, 2);
    float ex = expf(dot * rel_pri[r * HH + h] * 0.25f);   // / sqrt(16)

    float4 vv = *(const float4*)(vbase + (size_t)s * sstride + lane * 4);
    float* tp = tbuf + (size_t)d * D + lane * 4;
    asm volatile("red.global.add.v4.f32 [%0], {%1,%2,%3,%4};"
                 :: "l"(tp), "f"(vv.x * ex), "f"(vv.y * ex), "f"(vv.z * ex), "f"(vv.w * ex)
                 : "memory");
    if ((lane & 3) == 0)
        atomicAdd(&dbuf[(size_t)d * HH + h], ex);
}

// ---------------- launch ----------------------------------------------------
extern "C" void kernel_launch(void* const* d_in, const int* in_sizes, int n_in,
                              void* d_out, int out_size) {
    const float* h_a = (const float*)d_in[0];
    const float* h_b = (const float*)d_in[1];
    const int* src0 = (const int*)d_in[2]; const int* dst0 = (const int*)d_in[3];
    const int* src1 = (const int*)d_in[4]; const int* dst1 = (const int*)d_in[5];
    const int* src2 = (const int*)d_in[6]; const int* dst2 = (const int*)d_in[7];
    const float* Wk = (const float*)d_in[8];  const float* bk = (const float*)d_in[9];
    const float* Wv = (const float*)d_in[10]; const float* bv = (const float*)d_in[11];
    const float* Wq = (const float*)d_in[12]; const float* bq = (const float*)d_in[13];
    const float* Wa = (const float*)d_in[14]; const float* ba = (const float*)d_in[15];
    const float* rel_att = (const float*)d_in[16];
    const float* rel_msg = (const float*)d_in[17];
    const float* rel_pri = (const float*)d_in[18];
    const float* skip    = (const float*)d_in[19];
    float* out = (float*)d_out;

    zero_kernel<<<2048, 256>>>();
    wcat_kernel<<<(D * 640 + D * 384 + 255) / 256, 256>>>(Wk, bk, Wv, bv, Wq, bq, rel_att, rel_msg);

    int gm = (NN + 127) / 128;   // 782
    // fused projections: h_a -> [K0|K2|V0|V2|Qa], h_b -> [K1|V1|Qb]
    gemm_tc<<<dim3(gm, 10), 256>>>(h_a, 0, 2, nullptr, 4, nullptr, 0, nullptr, NN, 640, nullptr, nullptr, 0);
    gemm_tc<<<dim3(gm, 6),  256>>>(h_b, 0, 3, nullptr, 5, nullptr, 1, nullptr, NN, 384, nullptr, nullptr, 0);

    // fused edge softmax + aggregation (unnormalized; normalized in out-GEMM A-load)
    int eb = (EE + 7) / 8;
    edge_kernel<<<eb, 256>>>(0, src0, dst0, rel_pri);
    edge_kernel<<<eb, 256>>>(1, src1, dst1, rel_pri);
    edge_kernel<<<eb, 256>>>(2, src2, dst2, rel_pri);

    // output projections: A normalized on the fly, skip-mix epilogue
    gemm_tc<<<dim3(gm, 2), 256>>>(nullptr, 1, -1, Wa,         -1, ba,     -1, out,                  NN, 128, h_a, skip, 0);
    gemm_tc<<<dim3(gm, 2), 256>>>(nullptr, 2, -1, Wa + D * D, -1, ba + D, -1, out + (size_t)NN * D, NN, 128, h_b, skip, 1);
}

// round 7
// speedup vs baseline: 1.9226x; 1.2170x over previous
#include <cuda_runtime.h>
#include <cuda_bf16.h>
#include <math.h>
#include <stdint.h>

#define NN 100000
#define EE 500000
#define D  128
#define HH 8
#define DKH 16

// ===================== scratch ==============================================
__device__ float g_Pa[(size_t)NN * 640];   // [K_r0 | K_r2 | V_r0 | V_r2 | Q_a]
__device__ float g_Pb[(size_t)NN * 384];   // [K_r1 | V_r1 | Q_b]
__device__ float g_t[3][(size_t)NN * D];
__device__ float g_den[3][(size_t)NN * HH];
#define WT_ROWS (640 + 384 + 128 + 128)    // 1280
__device__ __nv_bfloat16 g_WtHi[WT_ROWS * D];   // W^T pre-split, [n][k]
__device__ __nv_bfloat16 g_WtLo[WT_ROWS * D];
__device__ float g_bias[WT_ROWS];
__device__ __nv_bfloat16 g_AHi[(size_t)2 * NN * D];  // h_a rows 0..NN-1, h_b rows NN..2NN-1
__device__ __nv_bfloat16 g_ALo[(size_t)2 * NN * D];

// ---------------- helpers ----------------------------------------------------
__device__ __forceinline__ void split2(float x, float y, uint32_t& hi, uint32_t& lo) {
    __nv_bfloat16 hx = __float2bfloat16(x), hy = __float2bfloat16(y);
    __nv_bfloat16 lx = __float2bfloat16(x - __bfloat162float(hx));
    __nv_bfloat16 ly = __float2bfloat16(y - __bfloat162float(hy));
    hi = ((uint32_t)*(uint16_t*)&hy << 16) | *(uint16_t*)&hx;
    lo = ((uint32_t)*(uint16_t*)&ly << 16) | *(uint16_t*)&lx;
}
__device__ __forceinline__ void mma_bf16(float* c, const uint32_t* a, const uint32_t* b) {
    asm volatile("mma.sync.aligned.m16n8k16.row.col.f32.bf16.bf16.f32 "
                 "{%0,%1,%2,%3},{%4,%5,%6,%7},{%8,%9},{%0,%1,%2,%3};"
                 : "+f"(c[0]), "+f"(c[1]), "+f"(c[2]), "+f"(c[3])
                 : "r"(a[0]), "r"(a[1]), "r"(a[2]), "r"(a[3]), "r"(b[0]), "r"(b[1]));
}

// ---------------- zero den + t every launch ---------------------------------
__global__ void zero_kernel() {
    const long T_TOT = 3L * NN * D, DEN_TOT = 3L * NN * HH;
    float4* tp = (float4*)&g_t[0][0];
    float4* dp = (float4*)&g_den[0][0];
    long stride = (long)gridDim.x * blockDim.x;
    long i0 = blockIdx.x * (long)blockDim.x + threadIdx.x;
    const float4 z = make_float4(0.f, 0.f, 0.f, 0.f);
    for (long i = i0; i < T_TOT / 4; i += stride) tp[i] = z;
    for (long i = i0; i < DEN_TOT / 4; i += stride) dp[i] = z;
}

// ---------------- pre-split activations to bf16 hi/lo ------------------------
__global__ void split_kernel(const float* __restrict__ h_a, const float* __restrict__ h_b) {
    size_t idx = (size_t)blockIdx.x * blockDim.x + threadIdx.x;   // one float4 each
    const size_t TOT4 = (size_t)2 * NN * D / 4;
    if (idx >= TOT4) return;
    size_t fo = idx * 4;
    const size_t HALF = (size_t)NN * D;
    float4 v = (fo < HALF) ? *(const float4*)(h_a + fo)
                           : *(const float4*)(h_b + (fo - HALF));
    uint32_t h01, l01, h23, l23;
    split2(v.x, v.y, h01, l01);
    split2(v.z, v.w, h23, l23);
    *(uint2*)&g_AHi[fo] = make_uint2(h01, h23);
    *(uint2*)&g_ALo[fo] = make_uint2(l01, l23);
}

// ---------------- build transposed, relation-folded, bf16-split weights -----
__global__ void wcat_kernel(const float* __restrict__ Wk, const float* __restrict__ bk,
                            const float* __restrict__ Wv, const float* __restrict__ bv,
                            const float* __restrict__ Wq, const float* __restrict__ bq,
                            const float* __restrict__ Wa, const float* __restrict__ ba,
                            const float* __restrict__ rel_att, const float* __restrict__ rel_msg) {
    int idx = blockIdx.x * blockDim.x + threadIdx.x;
    if (idx >= WT_ROWS * D) return;
    int u = idx / D;      // output column n (transposed row)
    int k = idx % D;      // input dim
    float val = 0.f, bval = 0.f;
    if (u >= 1024) {      // out-proj GEMMs: plain Wa transpose
        int which = (u >= 1152) ? 1 : 0;
        int n = u - 1024 - which * 128;
        val  = Wa[which * D * D + k * D + n];
        bval = ba[which * D + n];
    } else {
        int o, tsrc;
        if (u < 640) { o = u;       tsrc = 0; }
        else         { o = u - 640; tsrc = 1; }
        int seg = o >> 7, oo = o & 127;
        bool isQ = (tsrc == 0) ? (seg == 4) : (seg == 2);
        if (isQ) {
            val  = Wq[tsrc * D * D + k * D + oo];
            bval = bq[tsrc * D + oo];
        } else {
            int r; bool isV;
            if (tsrc == 0) { r = (seg == 0) ? 0 : (seg == 1) ? 2 : (seg == 2) ? 0 : 2; isV = (seg >= 2); }
            else           { r = 1; isV = (seg == 1); }
            const float* Wm  = isV ? Wv : Wk;
            const float* bm  = isV ? bv : bk;
            const float* rel = isV ? rel_msg : rel_att;
            int h = oo >> 4, e = oo & 15;
            const float* wrow = Wm + tsrc * D * D + k * D + h * DKH;
            const float* brow = bm + tsrc * D + h * DKH;
            const float* relm = rel + (r * HH + h) * DKH * DKH;
            float s = 0.f, sb = 0.f;
            #pragma unroll
            for (int d2 = 0; d2 < DKH; d2++) {
                float rv = relm[d2 * DKH + e];
                s  += wrow[d2] * rv;
                sb += brow[d2] * rv;
            }
            val = s; bval = sb;
        }
    }
    __nv_bfloat16 hi = __float2bfloat16(val);
    g_WtHi[u * D + k] = hi;
    g_WtLo[u * D + k] = __float2bfloat16(val - __bfloat162float(hi));
    if (k == 0) g_bias[u] = bval;
}

// ===================== bf16x3 mma.sync GEMM =================================
// C tile: rows [blockIdx.x*128, +128), cols [blockIdx.y*64, +64).
// amode: 0 = A from pre-split g_AHi/g_ALo (row offset aRow);
//        1 = t[1]/den[1]; 2 = 0.5*(t[0]/den[0] + t[2]/den[2])
__global__ void __launch_bounds__(256) gemm6(
    int amode, int aRow, int wtRow, int biasOff,
    float* Copt, int csel, int cStride, int M,
    const float* __restrict__ resid, const float* __restrict__ skipv, int skipIdx)
{
    __shared__ uint32_t As[2][128][20];   // [plane][m][kpair] stride 20 (conflict-free)
    __shared__ uint32_t Bs[2][64][20];

    int tid = threadIdx.x, lane = tid & 31, wid = tid >> 5;
    int warp_m = wid >> 1, warp_n = wid & 1;
    int g = lane >> 2, tg = lane & 3;
    int m0 = blockIdx.x * 128, n0 = blockIdx.y * 64;
    float* C = (csel == 0) ? g_Pa : (csel == 1) ? g_Pb : Copt;

    float acc[2][4][4];
    #pragma unroll
    for (int mt = 0; mt < 2; mt++)
        #pragma unroll
        for (int nt = 0; nt < 4; nt++)
            #pragma unroll
            for (int i = 0; i < 4; i++) acc[mt][nt][i] = 0.f;

    for (int k0 = 0; k0 < 4; k0++) {       // BK = 32 floats
        // ---- A tile ----
        if (amode == 0) {
            #pragma unroll
            for (int u = 0; u < 4; u++) {
                int flat = u * 256 + tid;          // 0..1023
                int plane = flat >> 9;
                int rem = flat & 511;
                int row = rem >> 2, part = rem & 3;
                int grow = m0 + row;
                uint4 val = make_uint4(0u, 0u, 0u, 0u);
                if (grow < M) {
                    const __nv_bfloat16* src = (plane ? g_ALo : g_AHi)
                        + ((size_t)(aRow + grow) << 7) + k0 * 32 + part * 8;
                    val = *(const uint4*)src;
                }
                *(uint4*)&As[plane][row][part * 4] = val;
            }
        } else {
            #pragma unroll
            for (int u = 0; u < 4; u++) {
                int flat = u * 256 + tid;          // 0..1023 float4 slots
                int row = flat >> 3, part = flat & 7;
                int grow = m0 + row;
                int col = k0 * 32 + part * 4;
                float4 v = make_float4(0.f, 0.f, 0.f, 0.f);
                if (grow < M) {
                    if (amode == 1) {
                        float4 t = *(const float4*)(g_t[1] + (size_t)grow * D + col);
                        float den = g_den[1][(size_t)grow * HH + (col >> 4)];
                        float dn = (den > 0.f) ? (1.f / den) : 0.f;
                        v = make_float4(t.x * dn, t.y * dn, t.z * dn, t.w * dn);
                    } else {
                        float4 t0 = *(const float4*)(g_t[0] + (size_t)grow * D + col);
                        float4 t2 = *(const float4*)(g_t[2] + (size_t)grow * D + col);
                        float den0 = g_den[0][(size_t)grow * HH + (col >> 4)];
                        float den2 = g_den[2][(size_t)grow * HH + (col >> 4)];
                        float d0 = (den0 > 0.f) ? (0.5f / den0) : 0.f;
                        float d2 = (den2 > 0.f) ? (0.5f / den2) : 0.f;
                        v = make_float4(t0.x * d0 + t2.x * d2, t0.y * d0 + t2.y * d2,
                                        t0.z * d0 + t2.z * d2, t0.w * d0 + t2.w * d2);
                    }
                }
                uint32_t h01, l01, h23, l23;
                split2(v.x, v.y, h01, l01);
                split2(v.z, v.w, h23, l23);
                *(uint2*)&As[0][row][part * 2] = make_uint2(h01, h23);
                *(uint2*)&As[1][row][part * 2] = make_uint2(l01, l23);
            }
        }
        // ---- B tile (pre-split bf16 in global) ----
        #pragma unroll
        for (int u = 0; u < 2; u++) {
            int flat = u * 256 + tid;              // 0..511
            int plane = flat >> 8;
            int rem = flat & 255;
            int row = rem >> 2, part = rem & 3;
            const __nv_bfloat16* src = (plane ? g_WtLo : g_WtHi)
                + (size_t)(wtRow + n0 + row) * D + k0 * 32 + part * 8;
            *(uint4*)&Bs[plane][row][part * 4] = *(const uint4*)src;
        }
        __syncthreads();

        // ---- mma: 2 k16 steps per BK ----
        #pragma unroll
        for (int ks = 0; ks < 2; ks++) {
            int kp0 = ks * 8;
            uint32_t ah[2][4], al[2][4], bh[4][2], bl[4][2];
            #pragma unroll
            for (int mt = 0; mt < 2; mt++) {
                int rb = warp_m * 32 + mt * 16;
                ah[mt][0] = As[0][rb + g][kp0 + tg];
                ah[mt][1] = As[0][rb + g + 8][kp0 + tg];
                ah[mt][2] = As[0][rb + g][kp0 + tg + 4];
                ah[mt][3] = As[0][rb + g + 8][kp0 + tg + 4];
                al[mt][0] = As[1][rb + g][kp0 + tg];
                al[mt][1] = As[1][rb + g + 8][kp0 + tg];
                al[mt][2] = As[1][rb + g][kp0 + tg + 4];
                al[mt][3] = As[1][rb + g + 8][kp0 + tg + 4];
            }
            #pragma unroll
            for (int nt = 0; nt < 4; nt++) {
                int cb = warp_n * 32 + nt * 8;
                bh[nt][0] = Bs[0][cb + g][kp0 + tg];
                bh[nt][1] = Bs[0][cb + g][kp0 + tg + 4];
                bl[nt][0] = Bs[1][cb + g][kp0 + tg];
                bl[nt][1] = Bs[1][cb + g][kp0 + tg + 4];
            }
            #pragma unroll
            for (int mt = 0; mt < 2; mt++)
                #pragma unroll
                for (int nt = 0; nt < 4; nt++) {
                    mma_bf16(acc[mt][nt], ah[mt], bh[nt]);
                    mma_bf16(acc[mt][nt], al[mt], bh[nt]);
                    mma_bf16(acc[mt][nt], ah[mt], bl[nt]);
                }
        }
        __syncthreads();
    }

    // ---- epilogue ----
    float alpha = 1.f, om = 0.f;
    if (resid) {
        float s = skipv[skipIdx];
        alpha = 1.f / (1.f + expf(-s));
        om = 1.f - alpha;
    }
    #pragma unroll
    for (int mt = 0; mt < 2; mt++)
        #pragma unroll
        for (int nt = 0; nt < 4; nt++) {
            int col = n0 + warp_n * 32 + nt * 8 + tg * 2;
            float b0 = g_bias[biasOff + col], b1 = g_bias[biasOff + col + 1];
            #pragma unroll
            for (int half = 0; half < 2; half++) {
                int row = m0 + warp_m * 32 + mt * 16 + g + half * 8;
                if (row >= M) continue;
                float v0 = acc[mt][nt][half * 2 + 0] + b0;
                float v1 = acc[mt][nt][half * 2 + 1] + b1;
                if (resid) {
                    v0 = v0 * alpha + resid[(size_t)row * D + col] * om;
                    v1 = v1 * alpha + resid[(size_t)row * D + col + 1] * om;
                }
                *(float2*)(C + (size_t)row * cStride + col) = make_float2(v0, v1);
            }
        }
}

// ---------------- fused edge pass (unchanged; at LTS roofline) ---------------
__global__ void edge_kernel(int r, const int* __restrict__ src, const int* __restrict__ dst,
                            const float* __restrict__ rel_pri) {
    int e = blockIdx.x * 8 + (threadIdx.x >> 5);
    if (e >= EE) return;
    int lane = threadIdx.x & 31;
    int h = lane >> 2;
    const float *kbase, *vbase, *qbase;
    int sstride, dstride;
    if (r == 0)      { kbase = g_Pa;       vbase = g_Pa + 256; qbase = g_Pb + 256; sstride = 640; dstride = 384; }
    else if (r == 1) { kbase = g_Pb;       vbase = g_Pb + 128; qbase = g_Pa + 512; sstride = 384; dstride = 640; }
    else             { kbase = g_Pa + 128; vbase = g_Pa + 384; qbase = g_Pb + 256; sstride = 640; dstride = 384; }
    float* tbuf = g_t[r];
    float* dbuf = g_den[r];
    int s = src[e], d = dst[e];
    float4 kv = *(const float4*)(kbase + (size_t)s * sstride + lane * 4);
    float4 qv = *(const float4*)(qbase + (size_t)d * dstride + lane * 4);
    float dot = kv.x * qv.x + kv.y * qv.y + kv.z * qv.z + kv.w * qv.w;
    dot += __shfl_xor_sync(0xffffffff, dot, 1);
    dot += __shfl_xor_sync(0xffffffff, dot, 2);
    float ex = expf(dot * rel_pri[r * HH + h] * 0.25f);
    float4 vv = *(const float4*)(vbase + (size_t)s * sstride + lane * 4);
    float* tp = tbuf + (size_t)d * D + lane * 4;
    asm volatile("red.global.add.v4.f32 [%0], {%1,%2,%3,%4};"
                 :: "l"(tp), "f"(vv.x * ex), "f"(vv.y * ex), "f"(vv.z * ex), "f"(vv.w * ex)
                 : "memory");
    if ((lane & 3) == 0)
        atomicAdd(&dbuf[(size_t)d * HH + h], ex);
}

// ---------------- launch ----------------------------------------------------
extern "C" void kernel_launch(void* const* d_in, const int* in_sizes, int n_in,
                              void* d_out, int out_size) {
    const float* h_a = (const float*)d_in[0];
    const float* h_b = (const float*)d_in[1];
    const int* src0 = (const int*)d_in[2]; const int* dst0 = (const int*)d_in[3];
    const int* src1 = (const int*)d_in[4]; const int* dst1 = (const int*)d_in[5];
    const int* src2 = (const int*)d_in[6]; const int* dst2 = (const int*)d_in[7];
    const float* Wk = (const float*)d_in[8];  const float* bk = (const float*)d_in[9];
    const float* Wv = (const float*)d_in[10]; const float* bv = (const float*)d_in[11];
    const float* Wq = (const float*)d_in[12]; const float* bq = (const float*)d_in[13];
    const float* Wa = (const float*)d_in[14]; const float* ba = (const float*)d_in[15];
    const float* rel_att = (const float*)d_in[16];
    const float* rel_msg = (const float*)d_in[17];
    const float* rel_pri = (const float*)d_in[18];
    const float* skip    = (const float*)d_in[19];
    float* out = (float*)d_out;

    zero_kernel<<<2048, 256>>>();
    wcat_kernel<<<(WT_ROWS * D + 255) / 256, 256>>>(Wk, bk, Wv, bv, Wq, bq, Wa, ba, rel_att, rel_msg);
    split_kernel<<<(int)(((size_t)2 * NN * D / 4 + 255) / 256), 256>>>(h_a, h_b);

    int gm = (NN + 127) / 128;   // 782
    // fused projections: h_a -> [K0|K2|V0|V2|Qa] (640 cols), h_b -> [K1|V1|Qb] (384)
    gemm6<<<dim3(gm, 10), 256>>>(0, 0,  0,    0,    nullptr, 0, 640, NN, nullptr, nullptr, 0);
    gemm6<<<dim3(gm, 6),  256>>>(0, NN, 640,  640,  nullptr, 1, 384, NN, nullptr, nullptr, 0);

    int eb = (EE + 7) / 8;
    edge_kernel<<<eb, 256>>>(0, src0, dst0, rel_pri);
    edge_kernel<<<eb, 256>>>(1, src1, dst1, rel_pri);
    edge_kernel<<<eb, 256>>>(2, src2, dst2, rel_pri);

    // output projections: A normalized on the fly, skip-mix epilogue
    gemm6<<<dim3(gm, 2), 256>>>(1, 0, 1024, 1024, out,                  2, 128, NN, h_a, skip, 0);
    gemm6<<<dim3(gm, 2), 256>>>(2, 0, 1152, 1152, out + (size_t)NN * D, 2, 128, NN, h_b, skip, 1);
}

// round 8
// speedup vs baseline: 2.1063x; 1.0955x over previous
#include <cuda_runtime.h>
#include <cuda_bf16.h>
#include <math.h>
#include <stdint.h>

#define NN 100000
#define EE 500000
#define D  128
#define HH 8
#define DKH 16

// ===================== scratch ==============================================
__device__ float g_Pa[(size_t)NN * 640];   // [K_r0 | V_r0 | K_r2 | V_r2 | Q_a]
__device__ float g_Pb[(size_t)NN * 384];   // [K_r1 | V_r1 | Q_b]
__device__ float g_t[3][(size_t)NN * D];
__device__ float g_den[3][(size_t)NN * HH];
#define WT_ROWS (640 + 384 + 128 + 128)    // 1280
__device__ __nv_bfloat16 g_WtHi[WT_ROWS * D];   // W^T pre-split, [n][k]
__device__ __nv_bfloat16 g_WtLo[WT_ROWS * D];
__device__ float g_bias[WT_ROWS];
__device__ __nv_bfloat16 g_AHi[(size_t)2 * NN * D];  // h_a rows 0..NN-1, h_b rows NN..
__device__ __nv_bfloat16 g_ALo[(size_t)2 * NN * D];
// CSR scratch
__device__ int g_deg[3][NN];
__device__ int g_off[3][NN];
__device__ int g_cur[3][NN];
__device__ int g_sid[3][EE];
__device__ int g_base[3];

// ---------------- helpers ----------------------------------------------------
__device__ __forceinline__ void split2(float x, float y, uint32_t& hi, uint32_t& lo) {
    __nv_bfloat16 hx = __float2bfloat16(x), hy = __float2bfloat16(y);
    __nv_bfloat16 lx = __float2bfloat16(x - __bfloat162float(hx));
    __nv_bfloat16 ly = __float2bfloat16(y - __bfloat162float(hy));
    hi = ((uint32_t)*(uint16_t*)&hy << 16) | *(uint16_t*)&hx;
    lo = ((uint32_t)*(uint16_t*)&ly << 16) | *(uint16_t*)&lx;
}
__device__ __forceinline__ void mma_bf16(float* c, const uint32_t* a, const uint32_t* b) {
    asm volatile("mma.sync.aligned.m16n8k16.row.col.f32.bf16.bf16.f32 "
                 "{%0,%1,%2,%3},{%4,%5,%6,%7},{%8,%9},{%0,%1,%2,%3};"
                 : "+f"(c[0]), "+f"(c[1]), "+f"(c[2]), "+f"(c[3])
                 : "r"(a[0]), "r"(a[1]), "r"(a[2]), "r"(a[3]), "r"(b[0]), "r"(b[1]));
}

// ---------------- zero CSR counters each launch ------------------------------
__global__ void zero_kernel() {
    int idx = blockIdx.x * blockDim.x + threadIdx.x;
    int* dp = &g_deg[0][0];
    if (idx < 3 * NN) dp[idx] = 0;
    if (idx < 3) g_base[idx] = 0;
}

// ---------------- pre-split activations to bf16 hi/lo ------------------------
__global__ void split_kernel(const float* __restrict__ h_a, const float* __restrict__ h_b) {
    size_t idx = (size_t)blockIdx.x * blockDim.x + threadIdx.x;   // one float4 each
    const size_t TOT4 = (size_t)2 * NN * D / 4;
    if (idx >= TOT4) return;
    size_t fo = idx * 4;
    const size_t HALF = (size_t)NN * D;
    float4 v = (fo < HALF) ? *(const float4*)(h_a + fo)
                           : *(const float4*)(h_b + (fo - HALF));
    uint32_t h01, l01, h23, l23;
    split2(v.x, v.y, h01, l01);
    split2(v.z, v.w, h23, l23);
    *(uint2*)&g_AHi[fo] = make_uint2(h01, h23);
    *(uint2*)&g_ALo[fo] = make_uint2(l01, l23);
}

// ---------------- build transposed, relation-folded, bf16-split weights -----
// g_Pa cols: [0,128)=K_r0 [128,256)=V_r0 [256,384)=K_r2 [384,512)=V_r2 [512,640)=Qa
__global__ void wcat_kernel(const float* __restrict__ Wk, const float* __restrict__ bk,
                            const float* __restrict__ Wv, const float* __restrict__ bv,
                            const float* __restrict__ Wq, const float* __restrict__ bq,
                            const float* __restrict__ Wa, const float* __restrict__ ba,
                            const float* __restrict__ rel_att, const float* __restrict__ rel_msg) {
    int idx = blockIdx.x * blockDim.x + threadIdx.x;
    if (idx >= WT_ROWS * D) return;
    int u = idx / D;      // output column n (transposed row)
    int k = idx % D;      // input dim
    float val = 0.f, bval = 0.f;
    if (u >= 1024) {      // out-proj GEMMs: plain Wa transpose
        int which = (u >= 1152) ? 1 : 0;
        int n = u - 1024 - which * 128;
        val  = Wa[which * D * D + k * D + n];
        bval = ba[which * D + n];
    } else {
        int o, tsrc;
        if (u < 640) { o = u;       tsrc = 0; }
        else         { o = u - 640; tsrc = 1; }
        int seg = o >> 7, oo = o & 127;
        bool isQ = (tsrc == 0) ? (seg == 4) : (seg == 2);
        if (isQ) {
            val  = Wq[tsrc * D * D + k * D + oo];
            bval = bq[tsrc * D + oo];
        } else {
            int r; bool isV;
            if (tsrc == 0) { r = (seg < 2) ? 0 : 2; isV = (seg & 1); }
            else           { r = 1; isV = (seg == 1); }
            const float* Wm  = isV ? Wv : Wk;
            const float* bm  = isV ? bv : bk;
            const float* rel = isV ? rel_msg : rel_att;
            int h = oo >> 4, e = oo & 15;
            const float* wrow = Wm + tsrc * D * D + k * D + h * DKH;
            const float* brow = bm + tsrc * D + h * DKH;
            const float* relm = rel + (r * HH + h) * DKH * DKH;
            float s = 0.f, sb = 0.f;
            #pragma unroll
            for (int d2 = 0; d2 < DKH; d2++) {
                float rv = relm[d2 * DKH + e];
                s  += wrow[d2] * rv;
                sb += brow[d2] * rv;
            }
            val = s; bval = sb;
        }
    }
    __nv_bfloat16 hi = __float2bfloat16(val);
    g_WtHi[u * D + k] = hi;
    g_WtLo[u * D + k] = __float2bfloat16(val - __bfloat162float(hi));
    if (k == 0) g_bias[u] = bval;
}

// ===================== CSR build ============================================
__global__ void hist_kernel(const int* __restrict__ d0, const int* __restrict__ d1,
                            const int* __restrict__ d2) {
    int idx = blockIdx.x * blockDim.x + threadIdx.x;
    if (idx >= 3 * EE) return;
    int r = idx / EE, e = idx - r * EE;
    const int* dp = (r == 0) ? d0 : (r == 1) ? d1 : d2;
    atomicAdd(&g_deg[r][dp[e]], 1);
}

__global__ void scan_kernel() {   // grid (98, 3), block 1024
    __shared__ int sh[1024];
    __shared__ int sbase;
    int r = blockIdx.y, tid = threadIdx.x;
    int i = blockIdx.x * 1024 + tid;
    int v = (i < NN) ? g_deg[r][i] : 0;
    sh[tid] = v;
    __syncthreads();
    for (int s = 1; s < 1024; s <<= 1) {
        int t = (tid >= s) ? sh[tid - s] : 0;
        __syncthreads();
        sh[tid] += t;
        __syncthreads();
    }
    if (tid == 1023) sbase = atomicAdd(&g_base[r], sh[1023]);
    __syncthreads();
    int off = sbase + sh[tid] - v;
    if (i < NN) { g_off[r][i] = off; g_cur[r][i] = off; }
}

__global__ void fill_kernel(const int* __restrict__ s0, const int* __restrict__ d0,
                            const int* __restrict__ s1, const int* __restrict__ d1,
                            const int* __restrict__ s2, const int* __restrict__ d2) {
    int idx = blockIdx.x * blockDim.x + threadIdx.x;
    if (idx >= 3 * EE) return;
    int r = idx / EE, e = idx - r * EE;
    const int* sp = (r == 0) ? s0 : (r == 1) ? s1 : s2;
    const int* dp = (r == 0) ? d0 : (r == 1) ? d1 : d2;
    int pos = atomicAdd(&g_cur[r][dp[e]], 1);
    g_sid[r][pos] = sp[e];
}

// ===================== dst-major edge aggregation ===========================
// one warp per (relation, dst): q loaded once, t/den accumulated in registers,
// written once -- no atomics, no scatter, no t/den zeroing.
__global__ void aggr_kernel(const float* __restrict__ rel_pri) {
    int gw = (blockIdx.x * blockDim.x + threadIdx.x) >> 5;
    if (gw >= 3 * NN) return;
    int r = gw / NN, d = gw - r * NN;
    int lane = threadIdx.x & 31, h = lane >> 2;
    const float *kbase, *vbase, *qbase;
    int ss, ds;
    if (r == 0)      { kbase = g_Pa;       vbase = g_Pa + 128; qbase = g_Pb + 256; ss = 640; ds = 384; }
    else if (r == 1) { kbase = g_Pb;       vbase = g_Pb + 128; qbase = g_Pa + 512; ss = 384; ds = 640; }
    else             { kbase = g_Pa + 256; vbase = g_Pa + 384; qbase = g_Pb + 256; ss = 640; ds = 384; }
    int off = g_off[r][d], deg = g_deg[r][d];
    float4 qv = *(const float4*)(qbase + (size_t)d * ds + lane * 4);
    float pri = rel_pri[r * HH + h] * 0.25f;   // / sqrt(16)
    float4 acc = make_float4(0.f, 0.f, 0.f, 0.f);
    float den = 0.f;
    const int* sp = g_sid[r] + off;
    for (int i0 = 0; i0 < deg; i0 += 32) {
        int n = deg - i0; if (n > 32) n = 32;
        int sid = (lane < n) ? sp[i0 + lane] : 0;
        for (int i = 0; i < n; i++) {
            int s = __shfl_sync(0xffffffffu, sid, i);
            float4 kv = *(const float4*)(kbase + (size_t)s * ss + lane * 4);
            float dot = kv.x * qv.x + kv.y * qv.y + kv.z * qv.z + kv.w * qv.w;
            dot += __shfl_xor_sync(0xffffffffu, dot, 1);
            dot += __shfl_xor_sync(0xffffffffu, dot, 2);
            float ex = expf(dot * pri);
            float4 vv = *(const float4*)(vbase + (size_t)s * ss + lane * 4);
            acc.x += vv.x * ex; acc.y += vv.y * ex;
            acc.z += vv.z * ex; acc.w += vv.w * ex;
            den += ex;
        }
    }
    *(float4*)(g_t[r] + (size_t)d * D + lane * 4) = acc;
    if ((lane & 3) == 0) g_den[r][(size_t)d * HH + h] = den;
}

// ===================== bf16x3 mma.sync GEMM =================================
// mode 1: merged projections (by<10 -> Pa strip, else Pb strip)
// mode 2: merged output projections (which = by>>1), t-normalize A, skip-mix
__global__ void __launch_bounds__(256) gemm7(
    int mode, const float* __restrict__ skipv,
    const float* __restrict__ ha, const float* __restrict__ hb, float* __restrict__ out)
{
    __shared__ uint32_t As[2][128][20];   // [plane][m][kpair] stride 20 (conflict-free)
    __shared__ uint32_t Bs[2][64][20];

    int by = blockIdx.y;
    int amode, aRow = 0, wtRow, biasOff, cStride, n0, skipIdx = 0;
    float* C;
    const float* resid = nullptr;
    if (mode == 1) {
        if (by < 10) { amode = 0; aRow = 0;  wtRow = 0;   biasOff = 0;   C = g_Pa; cStride = 640; n0 = by * 64; }
        else         { amode = 0; aRow = NN; wtRow = 640; biasOff = 640; C = g_Pb; cStride = 384; n0 = (by - 10) * 64; }
    } else {
        int which = by >> 1;
        n0 = (by & 1) * 64;
        amode = 1 + which;
        wtRow = 1024 + which * 128;
        biasOff = wtRow;
        cStride = 128;
        C = out + (size_t)which * NN * D;
        resid = which ? hb : ha;
        skipIdx = which;
    }

    int tid = threadIdx.x, lane = tid & 31, wid = tid >> 5;
    int warp_m = wid >> 1, warp_n = wid & 1;
    int g = lane >> 2, tg = lane & 3;
    int m0 = blockIdx.x * 128;
    const int M = NN;

    float acc[2][4][4];
    #pragma unroll
    for (int mt = 0; mt < 2; mt++)
        #pragma unroll
        for (int nt = 0; nt < 4; nt++)
            #pragma unroll
            for (int i = 0; i < 4; i++) acc[mt][nt][i] = 0.f;

    for (int k0 = 0; k0 < 4; k0++) {       // BK = 32 floats
        // ---- A tile ----
        if (amode == 0) {
            #pragma unroll
            for (int u = 0; u < 4; u++) {
                int flat = u * 256 + tid;          // 0..1023
                int plane = flat >> 9;
                int rem = flat & 511;
                int row = rem >> 2, part = rem & 3;
                int grow = m0 + row;
                uint4 val = make_uint4(0u, 0u, 0u, 0u);
                if (grow < M) {
                    const __nv_bfloat16* src = (plane ? g_ALo : g_AHi)
                        + ((size_t)(aRow + grow) << 7) + k0 * 32 + part * 8;
                    val = *(const uint4*)src;
                }
                *(uint4*)&As[plane][row][part * 4] = val;
            }
        } else {
            #pragma unroll
            for (int u = 0; u < 4; u++) {
                int flat = u * 256 + tid;          // 0..1023 float4 slots
                int row = flat >> 3, part = flat & 7;
                int grow = m0 + row;
                int col = k0 * 32 + part * 4;
                float4 v = make_float4(0.f, 0.f, 0.f, 0.f);
                if (grow < M) {
                    if (amode == 1) {
                        float4 t = *(const float4*)(g_t[1] + (size_t)grow * D + col);
                        float den = g_den[1][(size_t)grow * HH + (col >> 4)];
                        float dn = (den > 0.f) ? (1.f / den) : 0.f;
                        v = make_float4(t.x * dn, t.y * dn, t.z * dn, t.w * dn);
                    } else {
                        float4 t0 = *(const float4*)(g_t[0] + (size_t)grow * D + col);
                        float4 t2 = *(const float4*)(g_t[2] + (size_t)grow * D + col);
                        float den0 = g_den[0][(size_t)grow * HH + (col >> 4)];
                        float den2 = g_den[2][(size_t)grow * HH + (col >> 4)];
                        float d0 = (den0 > 0.f) ? (0.5f / den0) : 0.f;
                        float d2 = (den2 > 0.f) ? (0.5f / den2) : 0.f;
                        v = make_float4(t0.x * d0 + t2.x * d2, t0.y * d0 + t2.y * d2,
                                        t0.z * d0 + t2.z * d2, t0.w * d0 + t2.w * d2);
                    }
                }
                uint32_t h01, l01, h23, l23;
                split2(v.x, v.y, h01, l01);
                split2(v.z, v.w, h23, l23);
                *(uint2*)&As[0][row][part * 2] = make_uint2(h01, h23);
                *(uint2*)&As[1][row][part * 2] = make_uint2(l01, l23);
            }
        }
        // ---- B tile (pre-split bf16 in global) ----
        #pragma unroll
        for (int u = 0; u < 2; u++) {
            int flat = u * 256 + tid;              // 0..511
            int plane = flat >> 8;
            int rem = flat & 255;
            int row = rem >> 2, part = rem & 3;
            const __nv_bfloat16* src = (plane ? g_WtLo : g_WtHi)
                + (size_t)(wtRow + n0 + row) * D + k0 * 32 + part * 8;
            *(uint4*)&Bs[plane][row][part * 4] = *(const uint4*)src;
        }
        __syncthreads();

        // ---- mma: 2 k16 steps per BK ----
        #pragma unroll
        for (int ks = 0; ks < 2; ks++) {
            int kp0 = ks * 8;
            uint32_t ah[2][4], al[2][4], bh[4][2], bl[4][2];
            #pragma unroll
            for (int mt = 0; mt < 2; mt++) {
                int rb = warp_m * 32 + mt * 16;
                ah[mt][0] = As[0][rb + g][kp0 + tg];
                ah[mt][1] = As[0][rb + g + 8][kp0 + tg];
                ah[mt][2] = As[0][rb + g][kp0 + tg + 4];
                ah[mt][3] = As[0][rb + g + 8][kp0 + tg + 4];
                al[mt][0] = As[1][rb + g][kp0 + tg];
                al[mt][1] = As[1][rb + g + 8][kp0 + tg];
                al[mt][2] = As[1][rb + g][kp0 + tg + 4];
                al[mt][3] = As[1][rb + g + 8][kp0 + tg + 4];
            }
            #pragma unroll
            for (int nt = 0; nt < 4; nt++) {
                int cb = warp_n * 32 + nt * 8;
                bh[nt][0] = Bs[0][cb + g][kp0 + tg];
                bh[nt][1] = Bs[0][cb + g][kp0 + tg + 4];
                bl[nt][0] = Bs[1][cb + g][kp0 + tg];
                bl[nt][1] = Bs[1][cb + g][kp0 + tg + 4];
            }
            #pragma unroll
            for (int mt = 0; mt < 2; mt++)
                #pragma unroll
                for (int nt = 0; nt < 4; nt++) {
                    mma_bf16(acc[mt][nt], ah[mt], bh[nt]);
                    mma_bf16(acc[mt][nt], al[mt], bh[nt]);
                    mma_bf16(acc[mt][nt], ah[mt], bl[nt]);
                }
        }
        __syncthreads();
    }

    // ---- epilogue ----
    float alpha = 1.f, om = 0.f;
    if (resid) {
        float s = skipv[skipIdx];
        alpha = 1.f / (1.f + expf(-s));
        om = 1.f - alpha;
    }
    #pragma unroll
    for (int mt = 0; mt < 2; mt++)
        #pragma unroll
        for (int nt = 0; nt < 4; nt++) {
            int col = n0 + warp_n * 32 + nt * 8 + tg * 2;
            float b0 = g_bias[biasOff + col], b1 = g_bias[biasOff + col + 1];
            #pragma unroll
            for (int half = 0; half < 2; half++) {
                int row = m0 + warp_m * 32 + mt * 16 + g + half * 8;
                if (row >= M) continue;
                float v0 = acc[mt][nt][half * 2 + 0] + b0;
                float v1 = acc[mt][nt][half * 2 + 1] + b1;
                if (resid) {
                    v0 = v0 * alpha + resid[(size_t)row * D + col] * om;
                    v1 = v1 * alpha + resid[(size_t)row * D + col + 1] * om;
                }
                *(float2*)(C + (size_t)row * cStride + col) = make_float2(v0, v1);
            }
        }
}

// ---------------- launch ----------------------------------------------------
extern "C" void kernel_launch(void* const* d_in, const int* in_sizes, int n_in,
                              void* d_out, int out_size) {
    const float* h_a = (const float*)d_in[0];
    const float* h_b = (const float*)d_in[1];
    const int* src0 = (const int*)d_in[2]; const int* dst0 = (const int*)d_in[3];
    const int* src1 = (const int*)d_in[4]; const int* dst1 = (const int*)d_in[5];
    const int* src2 = (const int*)d_in[6]; const int* dst2 = (const int*)d_in[7];
    const float* Wk = (const float*)d_in[8];  const float* bk = (const float*)d_in[9];
    const float* Wv = (const float*)d_in[10]; const float* bv = (const float*)d_in[11];
    const float* Wq = (const float*)d_in[12]; const float* bq = (const float*)d_in[13];
    const float* Wa = (const float*)d_in[14]; const float* ba = (const float*)d_in[15];
    const float* rel_att = (const float*)d_in[16];
    const float* rel_msg = (const float*)d_in[17];
    const float* rel_pri = (const float*)d_in[18];
    const float* skip    = (const float*)d_in[19];
    float* out = (float*)d_out;

    zero_kernel<<<(3 * NN + 255) / 256, 256>>>();
    wcat_kernel<<<(WT_ROWS * D + 255) / 256, 256>>>(Wk, bk, Wv, bv, Wq, bq, Wa, ba, rel_att, rel_msg);
    split_kernel<<<(int)(((size_t)2 * NN * D / 4 + 255) / 256), 256>>>(h_a, h_b);

    // CSR build (deg -> offsets -> src lists)
    hist_kernel<<<(3 * EE + 255) / 256, 256>>>(dst0, dst1, dst2);
    scan_kernel<<<dim3((NN + 1023) / 1024, 3), 1024>>>();
    fill_kernel<<<(3 * EE + 255) / 256, 256>>>(src0, dst0, src1, dst1, src2, dst2);

    int gm = (NN + 127) / 128;   // 782
    // merged projections: h_a -> 640 cols of Pa, h_b -> 384 cols of Pb
    gemm7<<<dim3(gm, 16), 256>>>(1, skip, h_a, h_b, out);

    // dst-major fused softmax + aggregation (no atomics)
    aggr_kernel<<<(3 * NN * 32 + 255) / 256, 256>>>(rel_pri);

    // merged output projections with skip mixing
    gemm7<<<dim3(gm, 4), 256>>>(2, skip, h_a, h_b, out);
}

// round 9
// speedup vs baseline: 2.5362x; 1.2041x over previous
#include <cuda_runtime.h>
#include <cuda_bf16.h>
#include <math.h>
#include <stdint.h>

#define NN 100000
#define EE 500000
#define D  128
#define HH 8
#define DKH 16

// ===================== scratch ==============================================
__device__ float g_Pa[(size_t)NN * 640];   // [K_r0 | V_r0 | K_r2 | V_r2 | Q_a]
__device__ float g_Pb[(size_t)NN * 384];   // [K_r1 | V_r1 | Q_b]
__device__ float g_t[3][(size_t)NN * D];
__device__ float g_den[3][(size_t)NN * HH];
#define WT_ROWS (640 + 384 + 128 + 128)    // 1280
__device__ __nv_bfloat16 g_WtHi[WT_ROWS * D];   // W^T pre-split, [n][k]
__device__ __nv_bfloat16 g_WtLo[WT_ROWS * D];
__device__ float g_bias[WT_ROWS];
__device__ __nv_bfloat16 g_AHi[(size_t)2 * NN * D];  // h_a rows 0..NN-1, h_b rows NN..
__device__ __nv_bfloat16 g_ALo[(size_t)2 * NN * D];
// CSR scratch
__device__ int g_deg[3][NN];
__device__ int g_off[3][NN];
__device__ int g_cur[3][NN];
__device__ int g_sid[3][EE];
__device__ int g_base[3];

// ---------------- helpers ----------------------------------------------------
__device__ __forceinline__ void split2(float x, float y, uint32_t& hi, uint32_t& lo) {
    __nv_bfloat16 hx = __float2bfloat16(x), hy = __float2bfloat16(y);
    __nv_bfloat16 lx = __float2bfloat16(x - __bfloat162float(hx));
    __nv_bfloat16 ly = __float2bfloat16(y - __bfloat162float(hy));
    hi = ((uint32_t)*(uint16_t*)&hy << 16) | *(uint16_t*)&hx;
    lo = ((uint32_t)*(uint16_t*)&ly << 16) | *(uint16_t*)&lx;
}
__device__ __forceinline__ void mma_bf16(float* c, const uint32_t* a, const uint32_t* b) {
    asm volatile("mma.sync.aligned.m16n8k16.row.col.f32.bf16.bf16.f32 "
                 "{%0,%1,%2,%3},{%4,%5,%6,%7},{%8,%9},{%0,%1,%2,%3};"
                 : "+f"(c[0]), "+f"(c[1]), "+f"(c[2]), "+f"(c[3])
                 : "r"(a[0]), "r"(a[1]), "r"(a[2]), "r"(a[3]), "r"(b[0]), "r"(b[1]));
}

// ---------------- zero CSR counters each launch ------------------------------
__global__ void zero_kernel() {
    int idx = blockIdx.x * blockDim.x + threadIdx.x;
    int* dp = &g_deg[0][0];
    if (idx < 3 * NN) dp[idx] = 0;
    if (idx < 3) g_base[idx] = 0;
}

// ---------------- pre-split activations to bf16 hi/lo ------------------------
__global__ void split_kernel(const float* __restrict__ h_a, const float* __restrict__ h_b) {
    size_t idx = (size_t)blockIdx.x * blockDim.x + threadIdx.x;   // one float4 each
    const size_t TOT4 = (size_t)2 * NN * D / 4;
    if (idx >= TOT4) return;
    size_t fo = idx * 4;
    const size_t HALF = (size_t)NN * D;
    float4 v = (fo < HALF) ? *(const float4*)(h_a + fo)
                           : *(const float4*)(h_b + (fo - HALF));
    uint32_t h01, l01, h23, l23;
    split2(v.x, v.y, h01, l01);
    split2(v.z, v.w, h23, l23);
    *(uint2*)&g_AHi[fo] = make_uint2(h01, h23);
    *(uint2*)&g_ALo[fo] = make_uint2(l01, l23);
}

// ---------------- build transposed, relation-folded, bf16-split weights -----
__global__ void wcat_kernel(const float* __restrict__ Wk, const float* __restrict__ bk,
                            const float* __restrict__ Wv, const float* __restrict__ bv,
                            const float* __restrict__ Wq, const float* __restrict__ bq,
                            const float* __restrict__ Wa, const float* __restrict__ ba,
                            const float* __restrict__ rel_att, const float* __restrict__ rel_msg) {
    int idx = blockIdx.x * blockDim.x + threadIdx.x;
    if (idx >= WT_ROWS * D) return;
    int u = idx / D;      // output column n (transposed row)
    int k = idx % D;      // input dim
    float val = 0.f, bval = 0.f;
    if (u >= 1024) {      // out-proj GEMMs: plain Wa transpose
        int which = (u >= 1152) ? 1 : 0;
        int n = u - 1024 - which * 128;
        val  = Wa[which * D * D + k * D + n];
        bval = ba[which * D + n];
    } else {
        int o, tsrc;
        if (u < 640) { o = u;       tsrc = 0; }
        else         { o = u - 640; tsrc = 1; }
        int seg = o >> 7, oo = o & 127;
        bool isQ = (tsrc == 0) ? (seg == 4) : (seg == 2);
        if (isQ) {
            val  = Wq[tsrc * D * D + k * D + oo];
            bval = bq[tsrc * D + oo];
        } else {
            int r; bool isV;
            if (tsrc == 0) { r = (seg < 2) ? 0 : 2; isV = (seg & 1); }
            else           { r = 1; isV = (seg == 1); }
            const float* Wm  = isV ? Wv : Wk;
            const float* bm  = isV ? bv : bk;
            const float* rel = isV ? rel_msg : rel_att;
            int h = oo >> 4, e = oo & 15;
            const float* wrow = Wm + tsrc * D * D + k * D + h * DKH;
            const float* brow = bm + tsrc * D + h * DKH;
            const float* relm = rel + (r * HH + h) * DKH * DKH;
            float s = 0.f, sb = 0.f;
            #pragma unroll
            for (int d2 = 0; d2 < DKH; d2++) {
                float rv = relm[d2 * DKH + e];
                s  += wrow[d2] * rv;
                sb += brow[d2] * rv;
            }
            val = s; bval = sb;
        }
    }
    __nv_bfloat16 hi = __float2bfloat16(val);
    g_WtHi[u * D + k] = hi;
    g_WtLo[u * D + k] = __float2bfloat16(val - __bfloat162float(hi));
    if (k == 0) g_bias[u] = bval;
}

// ===================== CSR build ============================================
__global__ void hist_kernel(const int* __restrict__ d0, const int* __restrict__ d1,
                            const int* __restrict__ d2) {
    int idx = blockIdx.x * blockDim.x + threadIdx.x;
    if (idx >= 3 * EE) return;
    int r = idx / EE, e = idx - r * EE;
    const int* dp = (r == 0) ? d0 : (r == 1) ? d1 : d2;
    atomicAdd(&g_deg[r][dp[e]], 1);
}

__global__ void scan_kernel() {   // grid (98, 3), block 1024
    __shared__ int sh[1024];
    __shared__ int sbase;
    int r = blockIdx.y, tid = threadIdx.x;
    int i = blockIdx.x * 1024 + tid;
    int v = (i < NN) ? g_deg[r][i] : 0;
    sh[tid] = v;
    __syncthreads();
    for (int s = 1; s < 1024; s <<= 1) {
        int t = (tid >= s) ? sh[tid - s] : 0;
        __syncthreads();
        sh[tid] += t;
        __syncthreads();
    }
    if (tid == 1023) sbase = atomicAdd(&g_base[r], sh[1023]);
    __syncthreads();
    int off = sbase + sh[tid] - v;
    if (i < NN) { g_off[r][i] = off; g_cur[r][i] = off; }
}

__global__ void fill_kernel(const int* __restrict__ s0, const int* __restrict__ d0,
                            const int* __restrict__ s1, const int* __restrict__ d1,
                            const int* __restrict__ s2, const int* __restrict__ d2) {
    int idx = blockIdx.x * blockDim.x + threadIdx.x;
    if (idx >= 3 * EE) return;
    int r = idx / EE, e = idx - r * EE;
    const int* sp = (r == 0) ? s0 : (r == 1) ? s1 : s2;
    const int* dp = (r == 0) ? d0 : (r == 1) ? d1 : d2;
    int pos = atomicAdd(&g_cur[r][dp[e]], 1);
    g_sid[r][pos] = sp[e];
}

// ===================== dst-major edge aggregation ===========================
__global__ void aggr_kernel(const float* __restrict__ rel_pri) {
    int gw = (blockIdx.x * blockDim.x + threadIdx.x) >> 5;
    if (gw >= 3 * NN) return;
    int r = gw / NN, d = gw - r * NN;
    int lane = threadIdx.x & 31, h = lane >> 2;
    const float *kbase, *vbase, *qbase;
    int ss, ds;
    if (r == 0)      { kbase = g_Pa;       vbase = g_Pa + 128; qbase = g_Pb + 256; ss = 640; ds = 384; }
    else if (r == 1) { kbase = g_Pb;       vbase = g_Pb + 128; qbase = g_Pa + 512; ss = 384; ds = 640; }
    else             { kbase = g_Pa + 256; vbase = g_Pa + 384; qbase = g_Pb + 256; ss = 640; ds = 384; }
    int off = g_off[r][d], deg = g_deg[r][d];
    float4 qv = *(const float4*)(qbase + (size_t)d * ds + lane * 4);
    float pri = rel_pri[r * HH + h] * 0.25f;   // / sqrt(16)
    float4 acc = make_float4(0.f, 0.f, 0.f, 0.f);
    float den = 0.f;
    const int* sp = g_sid[r] + off;
    for (int i0 = 0; i0 < deg; i0 += 32) {
        int n = deg - i0; if (n > 32) n = 32;
        int sid = (lane < n) ? sp[i0 + lane] : 0;
        for (int i = 0; i < n; i++) {
            int s = __shfl_sync(0xffffffffu, sid, i);
            float4 kv = *(const float4*)(kbase + (size_t)s * ss + lane * 4);
            float dot = kv.x * qv.x + kv.y * qv.y + kv.z * qv.z + kv.w * qv.w;
            dot += __shfl_xor_sync(0xffffffffu, dot, 1);
            dot += __shfl_xor_sync(0xffffffffu, dot, 2);
            float ex = expf(dot * pri);
            float4 vv = *(const float4*)(vbase + (size_t)s * ss + lane * 4);
            acc.x += vv.x * ex; acc.y += vv.y * ex;
            acc.z += vv.z * ex; acc.w += vv.w * ex;
            den += ex;
        }
    }
    *(float4*)(g_t[r] + (size_t)d * D + lane * 4) = acc;
    if ((lane & 3) == 0) g_den[r][(size_t)d * HH + h] = den;
}

// ===================== A-stationary bf16x3 mma.sync GEMM ====================
// A tile (128 rows, full K=128, hi+lo planes) resident in SMEM; loop N-tiles.
// mode 1: by=0 -> Pa (10 tiles), by=1 -> Pb (6 tiles)
// mode 2: by=which output GEMM (2 tiles), t-normalized A, skip-mix epilogue
#define AS_STRIDE 68
#define AS_PLANE  (128 * AS_STRIDE)            // 8704 words
#define BS_OFF    (2 * AS_PLANE)               // 17408
#define BS_PLANE  (64 * AS_STRIDE)             // 4352
#define SMEM_WORDS (BS_OFF + 2 * BS_PLANE)     // 26112 words = 104448 B

__global__ void __launch_bounds__(256) gemm8(
    int mode, const float* __restrict__ skipv,
    const float* __restrict__ ha, const float* __restrict__ hb, float* __restrict__ out)
{
    extern __shared__ uint32_t sm[];
    int by = blockIdx.y;
    int amode, aRow = 0, wtRow, biasOff, cStride, numNT, skipIdx = 0;
    float* C;
    const float* resid = nullptr;
    if (mode == 1) {
        if (by == 0) { amode = 0; aRow = 0;  wtRow = 0;   biasOff = 0;   C = g_Pa; cStride = 640; numNT = 10; }
        else         { amode = 0; aRow = NN; wtRow = 640; biasOff = 640; C = g_Pb; cStride = 384; numNT = 6; }
    } else {
        int which = by;
        amode = 1 + which;
        wtRow = 1024 + which * 128;
        biasOff = wtRow;
        cStride = 128;
        numNT = 2;
        C = out + (size_t)which * NN * D;
        resid = which ? hb : ha;
        skipIdx = which;
    }

    int tid = threadIdx.x, lane = tid & 31, wid = tid >> 5;
    int warp_m = wid >> 1, warp_n = wid & 1;
    int g = lane >> 2, tg = lane & 3;
    int m0 = blockIdx.x * 128;
    const int M = NN;

    // ---- load A tile once (full K) ----
    if (amode == 0) {
        #pragma unroll
        for (int u = 0; u < 16; u++) {
            int flat = u * 256 + tid;          // 0..4095 uint4 slots
            int plane = flat >> 11;
            int rem = flat & 2047;
            int row = rem >> 4, part = rem & 15;
            int grow = m0 + row;
            uint4 val = make_uint4(0u, 0u, 0u, 0u);
            if (grow < M) {
                const __nv_bfloat16* src = (plane ? g_ALo : g_AHi)
                    + ((size_t)(aRow + grow) << 7) + part * 8;
                val = *(const uint4*)src;
            }
            *(uint4*)&sm[plane * AS_PLANE + row * AS_STRIDE + part * 4] = val;
        }
    } else {
        #pragma unroll
        for (int u = 0; u < 16; u++) {
            int flat = u * 256 + tid;          // 0..4095 float4 slots
            int row = flat >> 5, part = flat & 31;
            int grow = m0 + row;
            int col = part * 4;
            float4 v = make_float4(0.f, 0.f, 0.f, 0.f);
            if (grow < M) {
                if (amode == 1) {
                    float4 t = *(const float4*)(g_t[1] + (size_t)grow * D + col);
                    float den = g_den[1][(size_t)grow * HH + (col >> 4)];
                    float dn = (den > 0.f) ? (1.f / den) : 0.f;
                    v = make_float4(t.x * dn, t.y * dn, t.z * dn, t.w * dn);
                } else {
                    float4 t0 = *(const float4*)(g_t[0] + (size_t)grow * D + col);
                    float4 t2 = *(const float4*)(g_t[2] + (size_t)grow * D + col);
                    float den0 = g_den[0][(size_t)grow * HH + (col >> 4)];
                    float den2 = g_den[2][(size_t)grow * HH + (col >> 4)];
                    float d0 = (den0 > 0.f) ? (0.5f / den0) : 0.f;
                    float d2 = (den2 > 0.f) ? (0.5f / den2) : 0.f;
                    v = make_float4(t0.x * d0 + t2.x * d2, t0.y * d0 + t2.y * d2,
                                    t0.z * d0 + t2.z * d2, t0.w * d0 + t2.w * d2);
                }
            }
            uint32_t h01, l01, h23, l23;
            split2(v.x, v.y, h01, l01);
            split2(v.z, v.w, h23, l23);
            *(uint2*)&sm[row * AS_STRIDE + part * 2]            = make_uint2(h01, h23);
            *(uint2*)&sm[AS_PLANE + row * AS_STRIDE + part * 2] = make_uint2(l01, l23);
        }
    }
    __syncthreads();

    float alpha = 1.f, om = 0.f;
    if (resid) {
        float s = skipv[skipIdx];
        alpha = 1.f / (1.f + expf(-s));
        om = 1.f - alpha;
    }

    for (int nt = 0; nt < numNT; nt++) {
        int n0 = nt * 64;
        // ---- load B tile (pre-split bf16 in global, L2-resident) ----
        #pragma unroll
        for (int u = 0; u < 8; u++) {
            int flat = u * 256 + tid;          // 0..2047 uint4 slots
            int plane = flat >> 10;
            int rem = flat & 1023;
            int row = rem >> 4, part = rem & 15;
            const __nv_bfloat16* src = (plane ? g_WtLo : g_WtHi)
                + (size_t)(wtRow + n0 + row) * D + part * 8;
            *(uint4*)&sm[BS_OFF + plane * BS_PLANE + row * AS_STRIDE + part * 4] = *(const uint4*)src;
        }
        __syncthreads();

        float acc[2][4][4];
        #pragma unroll
        for (int mt = 0; mt < 2; mt++)
            #pragma unroll
            for (int ntt = 0; ntt < 4; ntt++)
                #pragma unroll
                for (int i = 0; i < 4; i++) acc[mt][ntt][i] = 0.f;

        #pragma unroll
        for (int kk = 0; kk < 8; kk++) {
            int kp0 = kk * 8;
            uint32_t ah[2][4], al[2][4], bh[4][2], bl[4][2];
            #pragma unroll
            for (int mt = 0; mt < 2; mt++) {
                int rb = warp_m * 32 + mt * 16;
                const uint32_t* A0 = sm;
                const uint32_t* A1 = sm + AS_PLANE;
                ah[mt][0] = A0[(rb + g) * AS_STRIDE + kp0 + tg];
                ah[mt][1] = A0[(rb + g + 8) * AS_STRIDE + kp0 + tg];
                ah[mt][2] = A0[(rb + g) * AS_STRIDE + kp0 + tg + 4];
                ah[mt][3] = A0[(rb + g + 8) * AS_STRIDE + kp0 + tg + 4];
                al[mt][0] = A1[(rb + g) * AS_STRIDE + kp0 + tg];
                al[mt][1] = A1[(rb + g + 8) * AS_STRIDE + kp0 + tg];
                al[mt][2] = A1[(rb + g) * AS_STRIDE + kp0 + tg + 4];
                al[mt][3] = A1[(rb + g + 8) * AS_STRIDE + kp0 + tg + 4];
            }
            #pragma unroll
            for (int ntt = 0; ntt < 4; ntt++) {
                int cb = warp_n * 32 + ntt * 8;
                const uint32_t* B0 = sm + BS_OFF;
                const uint32_t* B1 = sm + BS_OFF + BS_PLANE;
                bh[ntt][0] = B0[(cb + g) * AS_STRIDE + kp0 + tg];
                bh[ntt][1] = B0[(cb + g) * AS_STRIDE + kp0 + tg + 4];
                bl[ntt][0] = B1[(cb + g) * AS_STRIDE + kp0 + tg];
                bl[ntt][1] = B1[(cb + g) * AS_STRIDE + kp0 + tg + 4];
            }
            #pragma unroll
            for (int mt = 0; mt < 2; mt++)
                #pragma unroll
                for (int ntt = 0; ntt < 4; ntt++) {
                    mma_bf16(acc[mt][ntt], ah[mt], bh[ntt]);
                    mma_bf16(acc[mt][ntt], al[mt], bh[ntt]);
                    mma_bf16(acc[mt][ntt], ah[mt], bl[ntt]);
                }
        }
        __syncthreads();   // all warps done reading Bs before next tile load

        // ---- epilogue for this N-tile (registers only) ----
        #pragma unroll
        for (int mt = 0; mt < 2; mt++)
            #pragma unroll
            for (int ntt = 0; ntt < 4; ntt++) {
                int col = n0 + warp_n * 32 + ntt * 8 + tg * 2;
                float b0 = g_bias[biasOff + col], b1 = g_bias[biasOff + col + 1];
                #pragma unroll
                for (int half = 0; half < 2; half++) {
                    int row = m0 + warp_m * 32 + mt * 16 + g + half * 8;
                    if (row >= M) continue;
                    float v0 = acc[mt][ntt][half * 2 + 0] + b0;
                    float v1 = acc[mt][ntt][half * 2 + 1] + b1;
                    if (resid) {
                        v0 = v0 * alpha + resid[(size_t)row * D + col] * om;
                        v1 = v1 * alpha + resid[(size_t)row * D + col + 1] * om;
                    }
                    *(float2*)(C + (size_t)row * cStride + col) = make_float2(v0, v1);
                }
            }
    }
}

// ---------------- launch ----------------------------------------------------
extern "C" void kernel_launch(void* const* d_in, const int* in_sizes, int n_in,
                              void* d_out, int out_size) {
    const float* h_a = (const float*)d_in[0];
    const float* h_b = (const float*)d_in[1];
    const int* src0 = (const int*)d_in[2]; const int* dst0 = (const int*)d_in[3];
    const int* src1 = (const int*)d_in[4]; const int* dst1 = (const int*)d_in[5];
    const int* src2 = (const int*)d_in[6]; const int* dst2 = (const int*)d_in[7];
    const float* Wk = (const float*)d_in[8];  const float* bk = (const float*)d_in[9];
    const float* Wv = (const float*)d_in[10]; const float* bv = (const float*)d_in[11];
    const float* Wq = (const float*)d_in[12]; const float* bq = (const float*)d_in[13];
    const float* Wa = (const float*)d_in[14]; const float* ba = (const float*)d_in[15];
    const float* rel_att = (const float*)d_in[16];
    const float* rel_msg = (const float*)d_in[17];
    const float* rel_pri = (const float*)d_in[18];
    const float* skip    = (const float*)d_in[19];
    float* out = (float*)d_out;

    const int SMEM_BYTES = SMEM_WORDS * 4;   // 104448
    cudaFuncSetAttribute(gemm8, cudaFuncAttributeMaxDynamicSharedMemorySize, SMEM_BYTES);

    zero_kernel<<<(3 * NN + 255) / 256, 256>>>();
    wcat_kernel<<<(WT_ROWS * D + 255) / 256, 256>>>(Wk, bk, Wv, bv, Wq, bq, Wa, ba, rel_att, rel_msg);
    split_kernel<<<(int)(((size_t)2 * NN * D / 4 + 255) / 256), 256>>>(h_a, h_b);

    // CSR build (deg -> offsets -> src lists)
    hist_kernel<<<(3 * EE + 255) / 256, 256>>>(dst0, dst1, dst2);
    scan_kernel<<<dim3((NN + 1023) / 1024, 3), 1024>>>();
    fill_kernel<<<(3 * EE + 255) / 256, 256>>>(src0, dst0, src1, dst1, src2, dst2);

    int gm = (NN + 127) / 128;   // 782
    // merged A-stationary projections
    gemm8<<<dim3(gm, 2), 256, SMEM_BYTES>>>(1, skip, h_a, h_b, out);

    // dst-major fused softmax + aggregation (no atomics)
    aggr_kernel<<<(3 * NN * 32 + 255) / 256, 256>>>(rel_pri);

    // merged output projections with skip mixing
    gemm8<<<dim3(gm, 2), 256, SMEM_BYTES>>>(2, skip, h_a, h_b, out);
}

// round 10
// speedup vs baseline: 2.5883x; 1.0205x over previous
#include <cuda_runtime.h>
#include <cuda_bf16.h>
#include <math.h>
#include <stdint.h>

#define NN 100000
#define EE 500000
#define D  128
#define HH 8
#define DKH 16

// ===================== scratch ==============================================
__device__ float g_Pa[(size_t)NN * 640];   // [K_r0 | V_r0 | K_r2 | V_r2 | Q_a]
__device__ float g_Pb[(size_t)NN * 384];   // [K_r1 | V_r1 | Q_b]
__device__ float g_t[2][(size_t)NN * D];   // 0: t_a (rel1), 1: t_b (rel0+rel2, pre-normalized)
#define WT_ROWS (640 + 384 + 128 + 128)    // 1280
__device__ __nv_bfloat16 g_WtHi[WT_ROWS * D];   // W^T pre-split, [n][k]
__device__ __nv_bfloat16 g_WtLo[WT_ROWS * D];
__device__ float g_bias[WT_ROWS];
// CSR scratch
__device__ int g_deg[3][NN];
__device__ int g_off[3][NN];
__device__ int g_cur[3][NN];
__device__ int g_sid[3][EE];
__device__ int g_base[3];

// ---------------- helpers ----------------------------------------------------
__device__ __forceinline__ void split2(float x, float y, uint32_t& hi, uint32_t& lo) {
    __nv_bfloat16 hx = __float2bfloat16(x), hy = __float2bfloat16(y);
    __nv_bfloat16 lx = __float2bfloat16(x - __bfloat162float(hx));
    __nv_bfloat16 ly = __float2bfloat16(y - __bfloat162float(hy));
    hi = ((uint32_t)*(uint16_t*)&hy << 16) | *(uint16_t*)&hx;
    lo = ((uint32_t)*(uint16_t*)&ly << 16) | *(uint16_t*)&lx;
}
__device__ __forceinline__ void mma_bf16(float* c, const uint32_t* a, const uint32_t* b) {
    asm volatile("mma.sync.aligned.m16n8k16.row.col.f32.bf16.bf16.f32 "
                 "{%0,%1,%2,%3},{%4,%5,%6,%7},{%8,%9},{%0,%1,%2,%3};"
                 : "+f"(c[0]), "+f"(c[1]), "+f"(c[2]), "+f"(c[3])
                 : "r"(a[0]), "r"(a[1]), "r"(a[2]), "r"(a[3]), "r"(b[0]), "r"(b[1]));
}

// ---------------- zero CSR counters each launch ------------------------------
__global__ void zero_kernel() {
    int idx = blockIdx.x * blockDim.x + threadIdx.x;
    int* dp = &g_deg[0][0];
    if (idx < 3 * NN) dp[idx] = 0;
    if (idx < 3) g_base[idx] = 0;
}

// ---------------- build transposed, relation-folded, bf16-split weights -----
__global__ void wcat_kernel(const float* __restrict__ Wk, const float* __restrict__ bk,
                            const float* __restrict__ Wv, const float* __restrict__ bv,
                            const float* __restrict__ Wq, const float* __restrict__ bq,
                            const float* __restrict__ Wa, const float* __restrict__ ba,
                            const float* __restrict__ rel_att, const float* __restrict__ rel_msg) {
    int idx = blockIdx.x * blockDim.x + threadIdx.x;
    if (idx >= WT_ROWS * D) return;
    int u = idx / D;      // output column n (transposed row)
    int k = idx % D;      // input dim
    float val = 0.f, bval = 0.f;
    if (u >= 1024) {      // out-proj GEMMs: plain Wa transpose
        int which = (u >= 1152) ? 1 : 0;
        int n = u - 1024 - which * 128;
        val  = Wa[which * D * D + k * D + n];
        bval = ba[which * D + n];
    } else {
        int o, tsrc;
        if (u < 640) { o = u;       tsrc = 0; }
        else         { o = u - 640; tsrc = 1; }
        int seg = o >> 7, oo = o & 127;
        bool isQ = (tsrc == 0) ? (seg == 4) : (seg == 2);
        if (isQ) {
            val  = Wq[tsrc * D * D + k * D + oo];
            bval = bq[tsrc * D + oo];
        } else {
            int r; bool isV;
            if (tsrc == 0) { r = (seg < 2) ? 0 : 2; isV = (seg & 1); }
            else           { r = 1; isV = (seg == 1); }
            const float* Wm  = isV ? Wv : Wk;
            const float* bm  = isV ? bv : bk;
            const float* rel = isV ? rel_msg : rel_att;
            int h = oo >> 4, e = oo & 15;
            const float* wrow = Wm + tsrc * D * D + k * D + h * DKH;
            const float* brow = bm + tsrc * D + h * DKH;
            const float* relm = rel + (r * HH + h) * DKH * DKH;
            float s = 0.f, sb = 0.f;
            #pragma unroll
            for (int d2 = 0; d2 < DKH; d2++) {
                float rv = relm[d2 * DKH + e];
                s  += wrow[d2] * rv;
                sb += brow[d2] * rv;
            }
            val = s; bval = sb;
        }
    }
    __nv_bfloat16 hi = __float2bfloat16(val);
    g_WtHi[u * D + k] = hi;
    g_WtLo[u * D + k] = __float2bfloat16(val - __bfloat162float(hi));
    if (k == 0) g_bias[u] = bval;
}

// ===================== CSR build ============================================
__global__ void hist_kernel(const int* __restrict__ d0, const int* __restrict__ d1,
                            const int* __restrict__ d2) {
    int idx = blockIdx.x * blockDim.x + threadIdx.x;
    if (idx >= 3 * EE) return;
    int r = idx / EE, e = idx - r * EE;
    const int* dp = (r == 0) ? d0 : (r == 1) ? d1 : d2;
    atomicAdd(&g_deg[r][dp[e]], 1);
}

__global__ void scan_kernel() {   // grid (98, 3), block 1024
    __shared__ int sh[1024];
    __shared__ int sbase;
    int r = blockIdx.y, tid = threadIdx.x;
    int i = blockIdx.x * 1024 + tid;
    int v = (i < NN) ? g_deg[r][i] : 0;
    sh[tid] = v;
    __syncthreads();
    for (int s = 1; s < 1024; s <<= 1) {
        int t = (tid >= s) ? sh[tid - s] : 0;
        __syncthreads();
        sh[tid] += t;
        __syncthreads();
    }
    if (tid == 1023) sbase = atomicAdd(&g_base[r], sh[1023]);
    __syncthreads();
    int off = sbase + sh[tid] - v;
    if (i < NN) { g_off[r][i] = off; g_cur[r][i] = off; }
}

__global__ void fill_kernel(const int* __restrict__ s0, const int* __restrict__ d0,
                            const int* __restrict__ s1, const int* __restrict__ d1,
                            const int* __restrict__ s2, const int* __restrict__ d2) {
    int idx = blockIdx.x * blockDim.x + threadIdx.x;
    if (idx >= 3 * EE) return;
    int r = idx / EE, e = idx - r * EE;
    const int* sp = (r == 0) ? s0 : (r == 1) ? s1 : s2;
    const int* dp = (r == 0) ? d0 : (r == 1) ? d1 : d2;
    int pos = atomicAdd(&g_cur[r][dp[e]], 1);
    g_sid[r][pos] = sp[e];
}

// ===================== dst-major edge aggregation ===========================
__device__ __forceinline__ void edge_loop(const int* __restrict__ sp, int deg,
    const float* __restrict__ base, int stride, float4 qv, float pri, int lane,
    float4& acc, float& den)
{
    for (int i0 = 0; i0 < deg; i0 += 32) {
        int n = deg - i0; if (n > 32) n = 32;
        int sid = (lane < n) ? sp[i0 + lane] : 0;
        for (int i = 0; i < n; i++) {
            int s = __shfl_sync(0xffffffffu, sid, i);
            const float* row = base + (size_t)s * stride;
            float4 kv = *(const float4*)(row + lane * 4);
            float dot = kv.x * qv.x + kv.y * qv.y + kv.z * qv.z + kv.w * qv.w;
            dot += __shfl_xor_sync(0xffffffffu, dot, 1);
            dot += __shfl_xor_sync(0xffffffffu, dot, 2);
            float ex = expf(dot * pri);
            float4 vv = *(const float4*)(row + 128 + lane * 4);
            acc.x += vv.x * ex; acc.y += vv.y * ex;
            acc.z += vv.z * ex; acc.w += vv.w * ex;
            den += ex;
        }
    }
}

// one warp per (group, dst). group 0: rel1 -> t_a. group 1: rel0+rel2 -> t_b
// (shared q_b, combined + pre-normalized in registers).
__global__ void aggr_kernel(const float* __restrict__ rel_pri) {
    int gw = (blockIdx.x * blockDim.x + threadIdx.x) >> 5;
    if (gw >= 2 * NN) return;
    int grp = gw / NN, d = gw - grp * NN;
    int lane = threadIdx.x & 31, h = lane >> 2;
    float4 outv;
    if (grp == 0) {
        float4 qv = *(const float4*)(g_Pa + (size_t)d * 640 + 512 + lane * 4);
        float pri = rel_pri[HH + h] * 0.25f;   // / sqrt(16)
        float4 acc = make_float4(0.f, 0.f, 0.f, 0.f);
        float den = 0.f;
        edge_loop(g_sid[1] + g_off[1][d], g_deg[1][d], g_Pb, 384, qv, pri, lane, acc, den);
        float dn = (den > 0.f) ? (1.f / den) : 0.f;
        outv = make_float4(acc.x * dn, acc.y * dn, acc.z * dn, acc.w * dn);
    } else {
        float4 qv = *(const float4*)(g_Pb + (size_t)d * 384 + 256 + lane * 4);
        float4 a0 = make_float4(0.f, 0.f, 0.f, 0.f), a2 = make_float4(0.f, 0.f, 0.f, 0.f);
        float den0 = 0.f, den2 = 0.f;
        edge_loop(g_sid[0] + g_off[0][d], g_deg[0][d], g_Pa,       640, qv,
                  rel_pri[h] * 0.25f, lane, a0, den0);
        edge_loop(g_sid[2] + g_off[2][d], g_deg[2][d], g_Pa + 256, 640, qv,
                  rel_pri[2 * HH + h] * 0.25f, lane, a2, den2);
        float s0 = (den0 > 0.f) ? (0.5f / den0) : 0.f;
        float s2 = (den2 > 0.f) ? (0.5f / den2) : 0.f;
        outv = make_float4(a0.x * s0 + a2.x * s2, a0.y * s0 + a2.y * s2,
                           a0.z * s0 + a2.z * s2, a0.w * s0 + a2.w * s2);
    }
    *(float4*)(g_t[grp] + (size_t)d * D + lane * 4) = outv;
}

// ===================== A-stationary bf16x3 mma.sync GEMM ====================
// A tile (128 rows, full K=128) read fp32, split to hi/lo planes in SMEM once;
// loop N-tiles. mode 1 (proj): by 0/1 -> Pa tiles 0-4/5-9 (A=h_a); by 2 -> Pb
// tiles 0-5 (A=h_b). mode 2 (out): by=which, A=g_t[by], skip-mix epilogue.
#define AS_STRIDE 68
#define AS_PLANE  (128 * AS_STRIDE)            // 8704 words
#define BS_OFF    (2 * AS_PLANE)               // 17408
#define BS_PLANE  (64 * AS_STRIDE)             // 4352
#define SMEM_WORDS (BS_OFF + 2 * BS_PLANE)     // 26112 words = 104448 B

__global__ void __launch_bounds__(256) gemm9(
    int mode, const float* __restrict__ ha, const float* __restrict__ hb,
    const float* __restrict__ skipv, float* __restrict__ out)
{
    extern __shared__ uint32_t sm[];
    int by = blockIdx.y;
    const float* Asrc; int wtRow, cStride, nt0, nNT, skipIdx = 0;
    float* C;
    const float* resid = nullptr;
    if (mode == 1) {
        if (by == 0)      { Asrc = ha; wtRow = 0;   C = g_Pa; cStride = 640; nt0 = 0; nNT = 5; }
        else if (by == 1) { Asrc = ha; wtRow = 0;   C = g_Pa; cStride = 640; nt0 = 5; nNT = 5; }
        else              { Asrc = hb; wtRow = 640; C = g_Pb; cStride = 384; nt0 = 0; nNT = 6; }
    } else {
        Asrc = g_t[by]; wtRow = 1024 + by * 128; C = out + (size_t)by * NN * D;
        cStride = 128; nt0 = 0; nNT = 2;
        resid = by ? hb : ha; skipIdx = by;
    }
    int biasOff = wtRow;

    int tid = threadIdx.x, lane = tid & 31, wid = tid >> 5;
    int warp_m = wid >> 1, warp_n = wid & 1;
    int g = lane >> 2, tg = lane & 3;
    int m0 = blockIdx.x * 128;
    const int M = NN;

    // ---- load A tile once (fp32 -> split planes) ----
    #pragma unroll
    for (int u = 0; u < 16; u++) {
        int flat = u * 256 + tid;          // 0..4095 float4 slots
        int row = flat >> 5, part = flat & 31;
        int grow = m0 + row;
        float4 v = make_float4(0.f, 0.f, 0.f, 0.f);
        if (grow < M) v = *(const float4*)(Asrc + ((size_t)grow << 7) + part * 4);
        uint32_t h01, l01, h23, l23;
        split2(v.x, v.y, h01, l01);
        split2(v.z, v.w, h23, l23);
        *(uint2*)&sm[row * AS_STRIDE + part * 2]            = make_uint2(h01, h23);
        *(uint2*)&sm[AS_PLANE + row * AS_STRIDE + part * 2] = make_uint2(l01, l23);
    }
    __syncthreads();

    float alpha = 1.f, om = 0.f;
    if (resid) {
        float s = skipv[skipIdx];
        alpha = 1.f / (1.f + expf(-s));
        om = 1.f - alpha;
    }

    for (int nt = nt0; nt < nt0 + nNT; nt++) {
        int n0 = nt * 64;
        // ---- load B tile (pre-split bf16, L2-resident) ----
        #pragma unroll
        for (int u = 0; u < 8; u++) {
            int flat = u * 256 + tid;          // 0..2047 uint4 slots
            int plane = flat >> 10;
            int rem = flat & 1023;
            int row = rem >> 4, part = rem & 15;
            const __nv_bfloat16* src = (plane ? g_WtLo : g_WtHi)
                + (size_t)(wtRow + n0 + row) * D + part * 8;
            *(uint4*)&sm[BS_OFF + plane * BS_PLANE + row * AS_STRIDE + part * 4] = *(const uint4*)src;
        }
        __syncthreads();

        float acc[2][4][4];
        #pragma unroll
        for (int mt = 0; mt < 2; mt++)
            #pragma unroll
            for (int ntt = 0; ntt < 4; ntt++)
                #pragma unroll
                for (int i = 0; i < 4; i++) acc[mt][ntt][i] = 0.f;

        #pragma unroll
        for (int kk = 0; kk < 8; kk++) {
            int kp0 = kk * 8;
            uint32_t ah[2][4], al[2][4], bh[4][2], bl[4][2];
            #pragma unroll
            for (int mt = 0; mt < 2; mt++) {
                int rb = warp_m * 32 + mt * 16;
                const uint32_t* A0 = sm;
                const uint32_t* A1 = sm + AS_PLANE;
                ah[mt][0] = A0[(rb + g) * AS_STRIDE + kp0 + tg];
                ah[mt][1] = A0[(rb + g + 8) * AS_STRIDE + kp0 + tg];
                ah[mt][2] = A0[(rb + g) * AS_STRIDE + kp0 + tg + 4];
                ah[mt][3] = A0[(rb + g + 8) * AS_STRIDE + kp0 + tg + 4];
                al[mt][0] = A1[(rb + g) * AS_STRIDE + kp0 + tg];
                al[mt][1] = A1[(rb + g + 8) * AS_STRIDE + kp0 + tg];
                al[mt][2] = A1[(rb + g) * AS_STRIDE + kp0 + tg + 4];
                al[mt][3] = A1[(rb + g + 8) * AS_STRIDE + kp0 + tg + 4];
            }
            #pragma unroll
            for (int ntt = 0; ntt < 4; ntt++) {
                int cb = warp_n * 32 + ntt * 8;
                const uint32_t* B0 = sm + BS_OFF;
                const uint32_t* B1 = sm + BS_OFF + BS_PLANE;
                bh[ntt][0] = B0[(cb + g) * AS_STRIDE + kp0 + tg];
                bh[ntt][1] = B0[(cb + g) * AS_STRIDE + kp0 + tg + 4];
                bl[ntt][0] = B1[(cb + g) * AS_STRIDE + kp0 + tg];
                bl[ntt][1] = B1[(cb + g) * AS_STRIDE + kp0 + tg + 4];
            }
            #pragma unroll
            for (int mt = 0; mt < 2; mt++)
                #pragma unroll
                for (int ntt = 0; ntt < 4; ntt++) {
                    mma_bf16(acc[mt][ntt], ah[mt], bh[ntt]);
                    mma_bf16(acc[mt][ntt], al[mt], bh[ntt]);
                    mma_bf16(acc[mt][ntt], ah[mt], bl[ntt]);
                }
        }
        __syncthreads();   // all warps done reading Bs before next tile load

        // ---- epilogue for this N-tile ----
        #pragma unroll
        for (int mt = 0; mt < 2; mt++)
            #pragma unroll
            for (int ntt = 0; ntt < 4; ntt++) {
                int col = n0 + warp_n * 32 + ntt * 8 + tg * 2;
                float b0 = g_bias[biasOff + col], b1 = g_bias[biasOff + col + 1];
                #pragma unroll
                for (int half = 0; half < 2; half++) {
                    int row = m0 + warp_m * 32 + mt * 16 + g + half * 8;
                    if (row >= M) continue;
                    float v0 = acc[mt][ntt][half * 2 + 0] + b0;
                    float v1 = acc[mt][ntt][half * 2 + 1] + b1;
                    if (resid) {
                        v0 = v0 * alpha + resid[(size_t)row * D + col] * om;
                        v1 = v1 * alpha + resid[(size_t)row * D + col + 1] * om;
                    }
                    *(float2*)(C + (size_t)row * cStride + col) = make_float2(v0, v1);
                }
            }
    }
}

// ---------------- launch ----------------------------------------------------
extern "C" void kernel_launch(void* const* d_in, const int* in_sizes, int n_in,
                              void* d_out, int out_size) {
    const float* h_a = (const float*)d_in[0];
    const float* h_b = (const float*)d_in[1];
    const int* src0 = (const int*)d_in[2]; const int* dst0 = (const int*)d_in[3];
    const int* src1 = (const int*)d_in[4]; const int* dst1 = (const int*)d_in[5];
    const int* src2 = (const int*)d_in[6]; const int* dst2 = (const int*)d_in[7];
    const float* Wk = (const float*)d_in[8];  const float* bk = (const float*)d_in[9];
    const float* Wv = (const float*)d_in[10]; const float* bv = (const float*)d_in[11];
    const float* Wq = (const float*)d_in[12]; const float* bq = (const float*)d_in[13];
    const float* Wa = (const float*)d_in[14]; const float* ba = (const float*)d_in[15];
    const float* rel_att = (const float*)d_in[16];
    const float* rel_msg = (const float*)d_in[17];
    const float* rel_pri = (const float*)d_in[18];
    const float* skip    = (const float*)d_in[19];
    float* out = (float*)d_out;

    static cudaStream_t s2 = nullptr;
    static cudaEvent_t evFork = nullptr, evJoin = nullptr;
    if (s2 == nullptr) {
        cudaStreamCreateWithFlags(&s2, cudaStreamNonBlocking);
        cudaEventCreateWithFlags(&evFork, cudaEventDisableTiming);
        cudaEventCreateWithFlags(&evJoin, cudaEventDisableTiming);
    }

    const int SMEM_BYTES = SMEM_WORDS * 4;   // 104448
    cudaFuncSetAttribute(gemm9, cudaFuncAttributeMaxDynamicSharedMemorySize, SMEM_BYTES);

    // fork: CSR build on side stream, overlapped with weight prep + proj GEMM
    cudaEventRecord(evFork, 0);
    cudaStreamWaitEvent(s2, evFork, 0);
    zero_kernel<<<(3 * NN + 255) / 256, 256, 0, s2>>>();
    hist_kernel<<<(3 * EE + 255) / 256, 256, 0, s2>>>(dst0, dst1, dst2);
    scan_kernel<<<dim3((NN + 1023) / 1024, 3), 1024, 0, s2>>>();
    fill_kernel<<<(3 * EE + 255) / 256, 256, 0, s2>>>(src0, dst0, src1, dst1, src2, dst2);
    cudaEventRecord(evJoin, s2);

    // main stream: weights + projections
    wcat_kernel<<<(WT_ROWS * D + 255) / 256, 256>>>(Wk, bk, Wv, bv, Wq, bq, Wa, ba, rel_att, rel_msg);
    int gm = (NN + 127) / 128;   // 782
    gemm9<<<dim3(gm, 3), 256, SMEM_BYTES>>>(1, h_a, h_b, skip, out);

    // join: aggregation needs projections + CSR
    cudaStreamWaitEvent(0, evJoin, 0);
    aggr_kernel<<<(2 * NN * 32 + 255) / 256, 256>>>(rel_pri);

    // output projections with skip mixing
    gemm9<<<dim3(gm, 2), 256, SMEM_BYTES>>>(2, h_a, h_b, skip, out);
}

// round 12
// speedup vs baseline: 3.0843x; 1.1917x over previous
#include <cuda_runtime.h>
#include <cuda_bf16.h>
#include <cuda_fp16.h>
#include <math.h>
#include <stdint.h>

#define NN 100000
#define EE 500000
#define D  128
#define HH 8
#define DKH 16

// ===================== scratch ==============================================
// edge-phase node features in fp16 (only consumer is aggr_kernel)
__device__ __half g_Pa_h[(size_t)NN * 640];   // [K_r0 | V_r0 | K_r2 | V_r2 | Q_a]
__device__ __half g_Pb_h[(size_t)NN * 384];   // [K_r1 | V_r1 | Q_b]
__device__ float g_t[2][(size_t)NN * D];      // 0: t_a (rel1), 1: t_b (rel0+2, normalized)
#define WT_ROWS (640 + 384 + 128 + 128)       // 1280
__device__ __nv_bfloat16 g_WtHi[WT_ROWS * D]; // W^T pre-split, [n][k]
__device__ __nv_bfloat16 g_WtLo[WT_ROWS * D];
__device__ float g_bias[WT_ROWS];
// CSR scratch
__device__ int g_deg[3][NN];
__device__ int g_off[3][NN];
__device__ int g_cur[3][NN];
__device__ int g_sid[3][EE];
__device__ int g_base[3];

// ---------------- helpers ----------------------------------------------------
__device__ __forceinline__ void split2(float x, float y, uint32_t& hi, uint32_t& lo) {
    __nv_bfloat16 hx = __float2bfloat16(x), hy = __float2bfloat16(y);
    __nv_bfloat16 lx = __float2bfloat16(x - __bfloat162float(hx));
    __nv_bfloat16 ly = __float2bfloat16(y - __bfloat162float(hy));
    hi = ((uint32_t)*(uint16_t*)&hy << 16) | *(uint16_t*)&hx;
    lo = ((uint32_t)*(uint16_t*)&ly << 16) | *(uint16_t*)&lx;
}
__device__ __forceinline__ void mma_bf16(float* c, const uint32_t* a, const uint32_t* b) {
    asm volatile("mma.sync.aligned.m16n8k16.row.col.f32.bf16.bf16.f32 "
                 "{%0,%1,%2,%3},{%4,%5,%6,%7},{%8,%9},{%0,%1,%2,%3};"
                 : "+f"(c[0]), "+f"(c[1]), "+f"(c[2]), "+f"(c[3])
                 : "r"(a[0]), "r"(a[1]), "r"(a[2]), "r"(a[3]), "r"(b[0]), "r"(b[1]));
}
__device__ __forceinline__ float4 load_h4(const __half* p) {
    uint2 q = *(const uint2*)p;
    float2 a = __half22float2(*(__half2*)&q.x);
    float2 b = __half22float2(*(__half2*)&q.y);
    return make_float4(a.x, a.y, b.x, b.y);
}

// ---------------- zero CSR counters each launch ------------------------------
__global__ void zero_kernel() {
    int idx = blockIdx.x * blockDim.x + threadIdx.x;
    int* dp = &g_deg[0][0];
    if (idx < 3 * NN) dp[idx] = 0;
    if (idx < 3) g_base[idx] = 0;
}

// ---------------- build transposed, relation-folded, bf16-split weights -----
__global__ void wcat_kernel(const float* __restrict__ Wk, const float* __restrict__ bk,
                            const float* __restrict__ Wv, const float* __restrict__ bv,
                            const float* __restrict__ Wq, const float* __restrict__ bq,
                            const float* __restrict__ Wa, const float* __restrict__ ba,
                            const float* __restrict__ rel_att, const float* __restrict__ rel_msg) {
    int idx = blockIdx.x * blockDim.x + threadIdx.x;
    if (idx >= WT_ROWS * D) return;
    int u = idx / D;      // output column n (transposed row)
    int k = idx % D;      // input dim
    float val = 0.f, bval = 0.f;
    if (u >= 1024) {      // out-proj GEMMs: plain Wa transpose
        int which = (u >= 1152) ? 1 : 0;
        int n = u - 1024 - which * 128;
        val  = Wa[which * D * D + k * D + n];
        bval = ba[which * D + n];
    } else {
        int o, tsrc;
        if (u < 640) { o = u;       tsrc = 0; }
        else         { o = u - 640; tsrc = 1; }
        int seg = o >> 7, oo = o & 127;
        bool isQ = (tsrc == 0) ? (seg == 4) : (seg == 2);
        if (isQ) {
            val  = Wq[tsrc * D * D + k * D + oo];
            bval = bq[tsrc * D + oo];
        } else {
            int r; bool isV;
            if (tsrc == 0) { r = (seg < 2) ? 0 : 2; isV = (seg & 1); }
            else           { r = 1; isV = (seg == 1); }
            const float* Wm  = isV ? Wv : Wk;
            const float* bm  = isV ? bv : bk;
            const float* rel = isV ? rel_msg : rel_att;
            int h = oo >> 4, e = oo & 15;
            const float* wrow = Wm + tsrc * D * D + k * D + h * DKH;
            const float* brow = bm + tsrc * D + h * DKH;
            const float* relm = rel + (r * HH + h) * DKH * DKH;
            float s = 0.f, sb = 0.f;
            #pragma unroll
            for (int d2 = 0; d2 < DKH; d2++) {
                float rv = relm[d2 * DKH + e];
                s  += wrow[d2] * rv;
                sb += brow[d2] * rv;
            }
            val = s; bval = sb;
        }
    }
    __nv_bfloat16 hi = __float2bfloat16(val);
    g_WtHi[u * D + k] = hi;
    g_WtLo[u * D + k] = __float2bfloat16(val - __bfloat162float(hi));
    if (k == 0) g_bias[u] = bval;
}

// ===================== CSR build ============================================
__global__ void hist_kernel(const int* __restrict__ d0, const int* __restrict__ d1,
                            const int* __restrict__ d2) {
    int idx = blockIdx.x * blockDim.x + threadIdx.x;
    if (idx >= 3 * EE) return;
    int r = idx / EE, e = idx - r * EE;
    const int* dp = (r == 0) ? d0 : (r == 1) ? d1 : d2;
    atomicAdd(&g_deg[r][dp[e]], 1);
}

__global__ void scan_kernel() {   // grid (98, 3), block 1024
    __shared__ int sh[1024];
    __shared__ int sbase;
    int r = blockIdx.y, tid = threadIdx.x;
    int i = blockIdx.x * 1024 + tid;
    int v = (i < NN) ? g_deg[r][i] : 0;
    sh[tid] = v;
    __syncthreads();
    for (int s = 1; s < 1024; s <<= 1) {
        int t = (tid >= s) ? sh[tid - s] : 0;
        __syncthreads();
        sh[tid] += t;
        __syncthreads();
    }
    if (tid == 1023) sbase = atomicAdd(&g_base[r], sh[1023]);
    __syncthreads();
    int off = sbase + sh[tid] - v;
    if (i < NN) { g_off[r][i] = off; g_cur[r][i] = off; }
}

__global__ void fill_kernel(const int* __restrict__ s0, const int* __restrict__ d0,
                            const int* __restrict__ s1, const int* __restrict__ d1,
                            const int* __restrict__ s2, const int* __restrict__ d2) {
    int idx = blockIdx.x * blockDim.x + threadIdx.x;
    if (idx >= 3 * EE) return;
    int r = idx / EE, e = idx - r * EE;
    const int* sp = (r == 0) ? s0 : (r == 1) ? s1 : s2;
    const int* dp = (r == 0) ? d0 : (r == 1) ? d1 : d2;
    int pos = atomicAdd(&g_cur[r][dp[e]], 1);
    g_sid[r][pos] = sp[e];
}

// ===================== dst-major edge aggregation (fp16 gathers) ============
__device__ __forceinline__ void edge_loop(const int* __restrict__ sp, int deg,
    const __half* __restrict__ base, int stride, float4 qv, float pri, int lane,
    float4& acc, float& den)
{
    for (int i0 = 0; i0 < deg; i0 += 32) {
        int n = deg - i0; if (n > 32) n = 32;
        int sid = (lane < n) ? sp[i0 + lane] : 0;
        for (int i = 0; i < n; i++) {
            int s = __shfl_sync(0xffffffffu, sid, i);
            const __half* row = base + (size_t)s * stride;
            float4 kv = load_h4(row + lane * 4);
            float dot = kv.x * qv.x + kv.y * qv.y + kv.z * qv.z + kv.w * qv.w;
            dot += __shfl_xor_sync(0xffffffffu, dot, 1);
            dot += __shfl_xor_sync(0xffffffffu, dot, 2);
            float ex = expf(dot * pri);
            float4 vv = load_h4(row + 128 + lane * 4);
            acc.x += vv.x * ex; acc.y += vv.y * ex;
            acc.z += vv.z * ex; acc.w += vv.w * ex;
            den += ex;
        }
    }
}

// one warp per (group, dst). group 0: rel1 -> t_a. group 1: rel0+rel2 -> t_b
__global__ void aggr_kernel(const float* __restrict__ rel_pri) {
    int gw = (blockIdx.x * blockDim.x + threadIdx.x) >> 5;
    if (gw >= 2 * NN) return;
    int grp = gw / NN, d = gw - grp * NN;
    int lane = threadIdx.x & 31, h = lane >> 2;
    float4 outv;
    if (grp == 0) {
        float4 qv = load_h4(g_Pa_h + (size_t)d * 640 + 512 + lane * 4);
        float pri = rel_pri[HH + h] * 0.25f;   // / sqrt(16)
        float4 acc = make_float4(0.f, 0.f, 0.f, 0.f);
        float den = 0.f;
        edge_loop(g_sid[1] + g_off[1][d], g_deg[1][d], g_Pb_h, 384, qv, pri, lane, acc, den);
        float dn = (den > 0.f) ? (1.f / den) : 0.f;
        outv = make_float4(acc.x * dn, acc.y * dn, acc.z * dn, acc.w * dn);
    } else {
        float4 qv = load_h4(g_Pb_h + (size_t)d * 384 + 256 + lane * 4);
        float4 a0 = make_float4(0.f, 0.f, 0.f, 0.f), a2 = make_float4(0.f, 0.f, 0.f, 0.f);
        float den0 = 0.f, den2 = 0.f;
        edge_loop(g_sid[0] + g_off[0][d], g_deg[0][d], g_Pa_h,       640, qv,
                  rel_pri[h] * 0.25f, lane, a0, den0);
        edge_loop(g_sid[2] + g_off[2][d], g_deg[2][d], g_Pa_h + 256, 640, qv,
                  rel_pri[2 * HH + h] * 0.25f, lane, a2, den2);
        float s0 = (den0 > 0.f) ? (0.5f / den0) : 0.f;
        float s2 = (den2 > 0.f) ? (0.5f / den2) : 0.f;
        outv = make_float4(a0.x * s0 + a2.x * s2, a0.y * s0 + a2.y * s2,
                           a0.z * s0 + a2.z * s2, a0.w * s0 + a2.w * s2);
    }
    *(float4*)(g_t[grp] + (size_t)d * D + lane * 4) = outv;
}

// ===================== A-stationary bf16x3 mma.sync GEMM ====================
// mode 1 (proj): by 0/1 -> Pa_h tiles 0-4/5-9 (A=h_a); by 2 -> Pb_h tiles 0-5
//   (A=h_b). Epilogue converts to fp16.
// mode 2 (out): by=which, A=g_t[by], fp32 out with skip-mix epilogue.
#define AS_STRIDE 68
#define AS_PLANE  (128 * AS_STRIDE)            // 8704 words
#define BS_OFF    (2 * AS_PLANE)               // 17408
#define BS_PLANE  (64 * AS_STRIDE)             // 4352
#define SMEM_WORDS (BS_OFF + 2 * BS_PLANE)     // 26112 words = 104448 B

__global__ void __launch_bounds__(256) gemm10(
    int mode, const float* __restrict__ ha, const float* __restrict__ hb,
    const float* __restrict__ skipv, float* __restrict__ out)
{
    extern __shared__ uint32_t sm[];
    int by = blockIdx.y;
    const float* Asrc; int wtRow, cStride, nt0, nNT, skipIdx = 0;
    __half* Ch = nullptr;
    float* Cf = nullptr;
    const float* resid = nullptr;
    if (mode == 1) {
        if (by == 0)      { Asrc = ha; wtRow = 0;   Ch = g_Pa_h; cStride = 640; nt0 = 0; nNT = 5; }
        else if (by == 1) { Asrc = ha; wtRow = 0;   Ch = g_Pa_h; cStride = 640; nt0 = 5; nNT = 5; }
        else              { Asrc = hb; wtRow = 640; Ch = g_Pb_h; cStride = 384; nt0 = 0; nNT = 6; }
    } else {
        Asrc = g_t[by]; wtRow = 1024 + by * 128; Cf = out + (size_t)by * NN * D;
        cStride = 128; nt0 = 0; nNT = 2;
        resid = by ? hb : ha; skipIdx = by;
    }
    int biasOff = wtRow;

    int tid = threadIdx.x, lane = tid & 31, wid = tid >> 5;
    int warp_m = wid >> 1, warp_n = wid & 1;
    int g = lane >> 2, tg = lane & 3;
    int m0 = blockIdx.x * 128;
    const int M = NN;

    // ---- load A tile once (fp32 -> split planes) ----
    #pragma unroll
    for (int u = 0; u < 16; u++) {
        int flat = u * 256 + tid;          // 0..4095 float4 slots
        int row = flat >> 5, part = flat & 31;
        int grow = m0 + row;
        float4 v = make_float4(0.f, 0.f, 0.f, 0.f);
        if (grow < M) v = *(const float4*)(Asrc + ((size_t)grow << 7) + part * 4);
        uint32_t h01, l01, h23, l23;
        split2(v.x, v.y, h01, l01);
        split2(v.z, v.w, h23, l23);
        *(uint2*)&sm[row * AS_STRIDE + part * 2]            = make_uint2(h01, h23);
        *(uint2*)&sm[AS_PLANE + row * AS_STRIDE + part * 2] = make_uint2(l01, l23);
    }
    __syncthreads();

    float alpha = 1.f, om = 0.f;
    if (resid) {
        float s = skipv[skipIdx];
        alpha = 1.f / (1.f + expf(-s));
        om = 1.f - alpha;
    }

    for (int nt = nt0; nt < nt0 + nNT; nt++) {
        int n0 = nt * 64;
        // ---- load B tile (pre-split bf16, L2-resident) ----
        #pragma unroll
        for (int u = 0; u < 8; u++) {
            int flat = u * 256 + tid;          // 0..2047 uint4 slots
            int plane = flat >> 10;
            int rem = flat & 1023;
            int row = rem >> 4, part = rem & 15;
            const __nv_bfloat16* src = (plane ? g_WtLo : g_WtHi)
                + (size_t)(wtRow + n0 + row) * D + part * 8;
            *(uint4*)&sm[BS_OFF + plane * BS_PLANE + row * AS_STRIDE + part * 4] = *(const uint4*)src;
        }
        __syncthreads();

        float acc[2][4][4];
        #pragma unroll
        for (int mt = 0; mt < 2; mt++)
            #pragma unroll
            for (int ntt = 0; ntt < 4; ntt++)
                #pragma unroll
                for (int i = 0; i < 4; i++) acc[mt][ntt][i] = 0.f;

        #pragma unroll
        for (int kk = 0; kk < 8; kk++) {
            int kp0 = kk * 8;
            uint32_t ah[2][4], al[2][4], bh[4][2], bl[4][2];
            #pragma unroll
            for (int mt = 0; mt < 2; mt++) {
                int rb = warp_m * 32 + mt * 16;
                const uint32_t* A0 = sm;
                const uint32_t* A1 = sm + AS_PLANE;
                ah[mt][0] = A0[(rb + g) * AS_STRIDE + kp0 + tg];
                ah[mt][1] = A0[(rb + g + 8) * AS_STRIDE + kp0 + tg];
                ah[mt][2] = A0[(rb + g) * AS_STRIDE + kp0 + tg + 4];
                ah[mt][3] = A0[(rb + g + 8) * AS_STRIDE + kp0 + tg + 4];
                al[mt][0] = A1[(rb + g) * AS_STRIDE + kp0 + tg];
                al[mt][1] = A1[(rb + g + 8) * AS_STRIDE + kp0 + tg];
                al[mt][2] = A1[(rb + g) * AS_STRIDE + kp0 + tg + 4];
                al[mt][3] = A1[(rb + g + 8) * AS_STRIDE + kp0 + tg + 4];
            }
            #pragma unroll
            for (int ntt = 0; ntt < 4; ntt++) {
                int cb = warp_n * 32 + ntt * 8;
                const uint32_t* B0 = sm + BS_OFF;
                const uint32_t* B1 = sm + BS_OFF + BS_PLANE;
                bh[ntt][0] = B0[(cb + g) * AS_STRIDE + kp0 + tg];
                bh[ntt][1] = B0[(cb + g) * AS_STRIDE + kp0 + tg + 4];
                bl[ntt][0] = B1[(cb + g) * AS_STRIDE + kp0 + tg];
                bl[ntt][1] = B1[(cb + g) * AS_STRIDE + kp0 + tg + 4];
            }
            #pragma unroll
            for (int mt = 0; mt < 2; mt++)
                #pragma unroll
                for (int ntt = 0; ntt < 4; ntt++) {
                    mma_bf16(acc[mt][ntt], ah[mt], bh[ntt]);
                    mma_bf16(acc[mt][ntt], al[mt], bh[ntt]);
                    mma_bf16(acc[mt][ntt], ah[mt], bl[ntt]);
                }
        }
        __syncthreads();   // all warps done reading Bs before next tile load

        // ---- epilogue for this N-tile ----
        #pragma unroll
        for (int mt = 0; mt < 2; mt++)
            #pragma unroll
            for (int ntt = 0; ntt < 4; ntt++) {
                int col = n0 + warp_n * 32 + ntt * 8 + tg * 2;
                float b0 = g_bias[biasOff + col], b1 = g_bias[biasOff + col + 1];
                #pragma unroll
                for (int half = 0; half < 2; half++) {
                    int row = m0 + warp_m * 32 + mt * 16 + g + half * 8;
                    if (row >= M) continue;
                    float v0 = acc[mt][ntt][half * 2 + 0] + b0;
                    float v1 = acc[mt][ntt][half * 2 + 1] + b1;
                    if (mode == 1) {
                        *(__half2*)(Ch + (size_t)row * cStride + col) = __floats2half2_rn(v0, v1);
                    } else {
                        v0 = v0 * alpha + resid[(size_t)row * D + col] * om;
                        v1 = v1 * alpha + resid[(size_t)row * D + col + 1] * om;
                        *(float2*)(Cf + (size_t)row * cStride + col) = make_float2(v0, v1);
                    }
                }
            }
    }
}

// ---------------- launch ----------------------------------------------------
extern "C" void kernel_launch(void* const* d_in, const int* in_sizes, int n_in,
                              void* d_out, int out_size) {
    const float* h_a = (const float*)d_in[0];
    const float* h_b = (const float*)d_in[1];
    const int* src0 = (const int*)d_in[2]; const int* dst0 = (const int*)d_in[3];
    const int* src1 = (const int*)d_in[4]; const int* dst1 = (const int*)d_in[5];
    const int* src2 = (const int*)d_in[6]; const int* dst2 = (const int*)d_in[7];
    const float* Wk = (const float*)d_in[8];  const float* bk = (const float*)d_in[9];
    const float* Wv = (const float*)d_in[10]; const float* bv = (const float*)d_in[11];
    const float* Wq = (const float*)d_in[12]; const float* bq = (const float*)d_in[13];
    const float* Wa = (const float*)d_in[14]; const float* ba = (const float*)d_in[15];
    const float* rel_att = (const float*)d_in[16];
    const float* rel_msg = (const float*)d_in[17];
    const float* rel_pri = (const float*)d_in[18];
    const float* skip    = (const float*)d_in[19];
    float* out = (float*)d_out;

    static cudaStream_t s2 = nullptr;
    static cudaEvent_t evFork = nullptr, evJoin = nullptr;
    if (s2 == nullptr) {
        cudaStreamCreateWithFlags(&s2, cudaStreamNonBlocking);
        cudaEventCreateWithFlags(&evFork, cudaEventDisableTiming);
        cudaEventCreateWithFlags(&evJoin, cudaEventDisableTiming);
    }

    const int SMEM_BYTES = SMEM_WORDS * 4;   // 104448
    cudaFuncSetAttribute(gemm10, cudaFuncAttributeMaxDynamicSharedMemorySize, SMEM_BYTES);

    // fork: CSR build on side stream, overlapped with weight prep + proj GEMM
    cudaEventRecord(evFork, 0);
    cudaStreamWaitEvent(s2, evFork, 0);
    zero_kernel<<<(3 * NN + 255) / 256, 256, 0, s2>>>();
    hist_kernel<<<(3 * EE + 255) / 256, 256, 0, s2>>>(dst0, dst1, dst2);
    scan_kernel<<<dim3((NN + 1023) / 1024, 3), 1024, 0, s2>>>();
    fill_kernel<<<(3 * EE + 255) / 256, 256, 0, s2>>>(src0, dst0, src1, dst1, src2, dst2);
    cudaEventRecord(evJoin, s2);

    // main stream: weights + projections
    wcat_kernel<<<(WT_ROWS * D + 255) / 256, 256>>>(Wk, bk, Wv, bv, Wq, bq, Wa, ba, rel_att, rel_msg);
    int gm = (NN + 127) / 128;   // 782
    gemm10<<<dim3(gm, 3), 256, SMEM_BYTES>>>(1, h_a, h_b, skip, out);

    // join: aggregation needs projections + CSR
    cudaStreamWaitEvent(0, evJoin, 0);
    aggr_kernel<<<(2 * NN * 32 + 255) / 256, 256>>>(rel_pri);

    // output projections with skip mixing
    gemm10<<<dim3(gm, 2), 256, SMEM_BYTES>>>(2, h_a, h_b, skip, out);
}